// round 12
// baseline (speedup 1.0000x reference)
#include <cuda_runtime.h>
#include <cuda_bf16.h>
#include <cstdint>

// Problem constants (fixed by setup_inputs)
#define Bb 4
#define Tt 2048
#define Cc 768
#define Hh 12
#define DH 64
#define Mm (Bb * Tt)      // 8192
#define N3 (3 * Cc)       // 2304
#define NKSTEP (Cc / 16)  // 48

// ---------------------------------------------------------------------------
// Device scratch: bf16 hi/lo splits.
// x splits TRANSPOSED: [K][M]. W splits natural [K][N]. q/k/v: [B,H,T,D].
// ---------------------------------------------------------------------------
__device__ __nv_bfloat16 g_xh[(size_t)Cc * Mm], g_xl[(size_t)Cc * Mm];
__device__ __nv_bfloat16 g_wh[(size_t)Cc * N3], g_wl[(size_t)Cc * N3];
__device__ __nv_bfloat16 g_qh[(size_t)Bb * Hh * Tt * DH], g_ql[(size_t)Bb * Hh * Tt * DH];
__device__ __nv_bfloat16 g_kh[(size_t)Bb * Hh * Tt * DH], g_kl[(size_t)Bb * Hh * Tt * DH];
__device__ __nv_bfloat16 g_vh[(size_t)Bb * Hh * Tt * DH], g_vl[(size_t)Bb * Hh * Tt * DH];

// ---------------------------------------------------------------------------
// Helpers
// ---------------------------------------------------------------------------
__device__ __forceinline__ uint32_t smem_u32(const void* p) {
    uint32_t a;
    asm("{ .reg .u64 t; cvta.to.shared.u64 t, %1; cvt.u32.u64 %0, t; }"
        : "=r"(a) : "l"(p));
    return a;
}
__device__ __forceinline__ void ldsm4(uint32_t r[4], uint32_t a) {
    asm volatile("ldmatrix.sync.aligned.m8n8.x4.shared.b16 {%0,%1,%2,%3}, [%4];"
                 : "=r"(r[0]), "=r"(r[1]), "=r"(r[2]), "=r"(r[3]) : "r"(a));
}
__device__ __forceinline__ void ldsm4t(uint32_t r[4], uint32_t a) {
    asm volatile("ldmatrix.sync.aligned.m8n8.x4.trans.shared.b16 {%0,%1,%2,%3}, [%4];"
                 : "=r"(r[0]), "=r"(r[1]), "=r"(r[2]), "=r"(r[3]) : "r"(a));
}
__device__ __forceinline__ void mma16816(float* c, const uint32_t* a, uint32_t b0, uint32_t b1) {
    asm volatile(
        "mma.sync.aligned.m16n8k16.row.col.f32.bf16.bf16.f32 "
        "{%0,%1,%2,%3}, {%4,%5,%6,%7}, {%8,%9}, {%0,%1,%2,%3};"
        : "+f"(c[0]), "+f"(c[1]), "+f"(c[2]), "+f"(c[3])
        : "r"(a[0]), "r"(a[1]), "r"(a[2]), "r"(a[3]), "r"(b0), "r"(b1));
}
// Fast bf16x3 split: packed cvt; hi halves recovered by bit ops.
__device__ __forceinline__ void split_pack(float x0, float x1, uint32_t& hi, uint32_t& lo) {
    uint32_t h;
    asm("cvt.rn.bf16x2.f32 %0, %1, %2;" : "=r"(h) : "f"(x1), "f"(x0));
    const float h0 = __uint_as_float(h << 16);
    const float h1 = __uint_as_float(h & 0xFFFF0000u);
    uint32_t lw;
    asm("cvt.rn.bf16x2.f32 %0, %1, %2;" : "=r"(lw) : "f"(x1 - h1), "f"(x0 - h0));
    hi = h; lo = lw;
}

#define CP16(s, g) \
    asm volatile("cp.async.cg.shared.global [%0], [%1], 16;" :: "r"(s), "l"(g))
#define CP_COMMIT() asm volatile("cp.async.commit_group;" ::: "memory")
#define CP_WAIT0()  asm volatile("cp.async.wait_group 0;" ::: "memory")

#define SWZ(row, byteoff) ((byteoff) ^ (((row) & 7) << 4))

// ---------------------------------------------------------------------------
// cvt_x: fp32 x[M][K] -> bf16 hi/lo TRANSPOSED [K][M]
// ---------------------------------------------------------------------------
__global__ __launch_bounds__(256) void cvt_x(const float* __restrict__ x) {
    __shared__ float S[64][65];
    const int m0 = blockIdx.x * 64, k0 = blockIdx.y * 64;
    const int tid = threadIdx.x;
#pragma unroll
    for (int i = 0; i < 4; i++) {
        const int c = tid + i * 256;
        const int row = c >> 4;
        const int c4 = (c & 15) * 4;
        float4 v = *(const float4*)&x[(size_t)(m0 + row) * Cc + k0 + c4];
        S[row][c4] = v.x; S[row][c4 + 1] = v.y; S[row][c4 + 2] = v.z; S[row][c4 + 3] = v.w;
    }
    __syncthreads();
#pragma unroll
    for (int i = 0; i < 2; i++) {
        const int c = tid + i * 256;
        const int k = c >> 3;
        const int mc = c & 7;
        uint32_t hw[4], lw[4];
#pragma unroll
        for (int e = 0; e < 4; e++)
            split_pack(S[mc * 8 + 2 * e][k], S[mc * 8 + 2 * e + 1][k], hw[e], lw[e]);
        const size_t g = (size_t)(k0 + k) * Mm + m0 + mc * 8;
        *(uint4*)&g_xh[g] = make_uint4(hw[0], hw[1], hw[2], hw[3]);
        *(uint4*)&g_xl[g] = make_uint4(lw[0], lw[1], lw[2], lw[3]);
    }
}
__global__ __launch_bounds__(256) void cvt_w(const float* __restrict__ W) {
    const size_t base = ((size_t)blockIdx.x * 256 + threadIdx.x) * 4;
    float4 v = *(const float4*)&W[base];
    uint32_t h01, l01, h23, l23;
    split_pack(v.x, v.y, h01, l01);
    split_pack(v.z, v.w, h23, l23);
    *(uint2*)&g_wh[base] = make_uint2(h01, h23);
    *(uint2*)&g_wl[base] = make_uint2(l01, l23);
}

// ---------------------------------------------------------------------------
// Kernel 1: qkv = x @ W + b via mma.sync bf16x3 (unchanged from R9).
// 128x128 block, 128 thr, 4 warps (2m x 2n), warp 64x64.
// 64KB dynamic smem: 2 super-stages x 32KB (each 2 x 16KB sub-stages).
// ---------------------------------------------------------------------------
__global__ __launch_bounds__(128) void qkv_mma(const float* __restrict__ bias) {
    extern __shared__ __align__(128) uint8_t smd[];
    const uint32_t uS = smem_u32(smd);

    const int tid = threadIdx.x;
    const int l   = tid & 31;
    const int w   = tid >> 5;
    const int wm  = w >> 1;
    const int wn  = w & 1;
    const int m0  = blockIdx.y * 128;
    const int n0  = blockIdx.x * 128;

    float acc[4][8][4];
#pragma unroll
    for (int i = 0; i < 4; i++)
#pragma unroll
        for (int j = 0; j < 8; j++)
#pragma unroll
            for (int r = 0; r < 4; r++) acc[i][j][r] = 0.f;

    const int cr = tid >> 3;
    const int cc = (tid & 7) * 2;
    const uint32_t so0 = (uint32_t)SWZ(cr, cr * 256 + cc * 16);
    const uint32_t so1 = (uint32_t)SWZ(cr, cr * 256 + cc * 16 + 16);

#define QKV_SUB(kb, bofs) do {                                                \
    const int _k = (kb) * 16 + cr;                                            \
    const uint32_t _b = uS + (bofs);                                          \
    const size_t _ga = (size_t)_k * Mm + m0 + cc * 8;                         \
    const size_t _gb = (size_t)_k * N3 + n0 + cc * 8;                         \
    CP16(_b + so0,         g_xh + _ga);                                       \
    CP16(_b + so1,         g_xh + _ga + 8);                                   \
    CP16(_b + 4096 + so0,  g_xl + _ga);                                       \
    CP16(_b + 4096 + so1,  g_xl + _ga + 8);                                   \
    CP16(_b + 8192 + so0,  g_wh + _gb);                                       \
    CP16(_b + 8192 + so1,  g_wh + _gb + 8);                                   \
    CP16(_b + 12288 + so0, g_wl + _gb);                                       \
    CP16(_b + 12288 + so1, g_wl + _gb + 8);                                   \
} while (0)

#define QKV_ISSUE2(kb, sst) do {                                              \
    QKV_SUB(kb, (sst) * 32768);                                               \
    QKV_SUB((kb) + 1, (sst) * 32768 + 16384);                                 \
    CP_COMMIT();                                                              \
} while (0)

    const int arow = (l & 7) + 8 * (l >> 4);
    const int abyt = wm * 128 + ((l >> 3) & 1) * 16;
    const int brow = (l & 15);
    const int bbyt = wn * 128 + (l >> 4) * 16;

    QKV_ISSUE2(0, 0);

    for (int kb2 = 0; kb2 < NKSTEP / 2; kb2++) {       // 24 rounds
        CP_WAIT0();
        __syncthreads();
        if (kb2 + 1 < NKSTEP / 2) QKV_ISSUE2(2 * (kb2 + 1), (kb2 + 1) & 1);

        const uint32_t superb = uS + (kb2 & 1) * 32768;
#pragma unroll
        for (int sub = 0; sub < 2; sub++) {
            const uint32_t sb = superb + sub * 16384;
            uint32_t fa[2][4][4], fb[2][4][4];
#pragma unroll
            for (int sp = 0; sp < 2; sp++) {
#pragma unroll
                for (int mt = 0; mt < 4; mt++)
                    ldsm4t(fa[sp][mt], sb + sp * 4096 + SWZ(arow, arow * 256 + abyt + mt * 32));
#pragma unroll
                for (int g = 0; g < 4; g++)
                    ldsm4t(fb[sp][g], sb + 8192 + sp * 4096 + SWZ(brow, brow * 256 + bbyt + g * 32));
            }

#pragma unroll
            for (int mt = 0; mt < 4; mt++)
#pragma unroll
                for (int nt = 0; nt < 8; nt++) {
                    const int g = nt >> 1, i2 = (nt & 1) * 2;
                    mma16816(acc[mt][nt], fa[0][mt], fb[0][g][i2], fb[0][g][i2 + 1]);
                    mma16816(acc[mt][nt], fa[0][mt], fb[1][g][i2], fb[1][g][i2 + 1]);
                    mma16816(acc[mt][nt], fa[1][mt], fb[0][g][i2], fb[0][g][i2 + 1]);
                }
        }
    }

    // ---- Epilogue ----
    const int which = n0 / Cc;
    const int nloc0 = n0 - which * Cc;
    const float scale = (which == 0) ? 0.125f : 1.0f;
    __nv_bfloat16* dh = (which == 0) ? g_qh : (which == 1) ? g_kh : g_vh;
    __nv_bfloat16* dl = (which == 0) ? g_ql : (which == 1) ? g_kl : g_vl;

    const int mrow = m0 + wm * 64 + (l >> 2);
    const int b_   = mrow >> 11;
#pragma unroll
    for (int mt = 0; mt < 4; mt++) {
        const int t1 = (mrow + mt * 16) & (Tt - 1);
#pragma unroll
        for (int nt = 0; nt < 8; nt++) {
            const int n  = nloc0 + wn * 64 + nt * 8 + 2 * (l & 3);
            const int hh = n >> 6;
            const int d  = n & 63;
            const float b0 = bias[which * Cc + n];
            const float b1 = bias[which * Cc + n + 1];
            uint32_t h01, l01, h23, l23;
            split_pack((acc[mt][nt][0] + b0) * scale, (acc[mt][nt][1] + b1) * scale, h01, l01);
            split_pack((acc[mt][nt][2] + b0) * scale, (acc[mt][nt][3] + b1) * scale, h23, l23);
            const size_t i1 = (((size_t)b_ * Hh + hh) * Tt + t1) * DH + d;
            const size_t i2 = i1 + (size_t)8 * DH;
            *(uint32_t*)&dh[i1] = h01;  *(uint32_t*)&dl[i1] = l01;
            *(uint32_t*)&dh[i2] = h23;  *(uint32_t*)&dl[i2] = l23;
        }
    }
}

// ---------------------------------------------------------------------------
// Kernel 2: causal ReLU attention, BQ=64, bf16x3, 256 threads (8 warps).
// Warp groups: A (w<4) handles even 32-row kv sub-tiles, B (w>=4) odd ones.
// Each group accumulates partial O; merged via smem at the end.
// 80KB dynamic smem: ring 2 x 32KB (each 2 x 16KB: K_hi +0, K_lo +4096,
// V_hi +8192, V_lo +12288) + Q tile at 65536 (hi) / 73728 (lo).
// Q fragments re-ldsm'd per super-stage (keeps live regs < 128, 2 blocks/SM).
// ---------------------------------------------------------------------------
__global__ __launch_bounds__(256, 2) void attn_mma(float* __restrict__ out)
{
    extern __shared__ __align__(128) uint8_t smd[];
    const uint32_t uS = smem_u32(smd);
    const uint32_t uQ = uS + 65536;

    const int tid = threadIdx.x;
    const int l   = tid & 31;
    const int w   = tid >> 5;
    const int wq  = w & 3;          // q-row group within warp-group
    const int grp = w >> 2;         // 0 = even sub-tiles, 1 = odd
    const int qt  = (gridDim.x - 1) - blockIdx.x;    // 0..31, long first
    const int h   = blockIdx.y;
    const int b   = blockIdx.z;

    const size_t hb = ((size_t)b * Hh + h) * (size_t)Tt * DH;

#define ATT_ISSUE2(j64, sst) do {                                           \
    const uint32_t _sb = uS + (sst) * 32768;                                \
    _Pragma("unroll")                                                       \
    for (int _i = 0; _i < 2; _i++) {                                        \
        const int _c = tid + _i * 256;       /* 0..511 */                   \
        const int _row = _c >> 3;            /* 0..63  */                   \
        const int _c16 = _c & 7;                                            \
        const int _sr  = _row & 31;                                         \
        const uint32_t _so = ((_row & 32) ? 16384u : 0u)                    \
                           + SWZ(_sr, _sr * 128 + _c16 * 16);               \
        const size_t _g = hb + (size_t)((j64) * 64 + _row) * DH + _c16 * 8; \
        CP16(_sb + _so,         g_kh + _g);                                 \
        CP16(_sb + 4096 + _so,  g_kl + _g);                                 \
        CP16(_sb + 8192 + _so,  g_vh + _g);                                 \
        CP16(_sb + 12288 + _so, g_vl + _g);                                 \
    }                                                                       \
    CP_COMMIT();                                                            \
} while (0)

    ATT_ISSUE2(0, 0);                 // first 64 kv rows -> super-stage 0

    // Q tile (64 rows, hi+lo) -> smem
#pragma unroll
    for (int i = 0; i < 2; i++) {
        const int c   = tid + i * 256;       // 0..511
        const int row = c >> 3;
        const int c16 = c & 7;
        const size_t g = hb + (size_t)(qt * 64 + row) * DH + c16 * 8;
        const int so = SWZ(row, row * 128 + c16 * 16);
        *(uint4*)(smd + 65536 + so) = *(const uint4*)&g_qh[g];
        *(uint4*)(smd + 73728 + so) = *(const uint4*)&g_ql[g];
    }

    float o[8][4];
#pragma unroll
    for (int i = 0; i < 8; i++)
#pragma unroll
        for (int r = 0; r < 4; r++) o[i][r] = 0.f;

    const int rowg = qt * 64 + wq * 16 + (l >> 2);

    for (int jo = 0; jo <= qt; jo++) {
        CP_WAIT0();
        __syncthreads();              // stage ready; also covers Q on jo==0
        if (jo < qt) ATT_ISSUE2(jo + 1, (jo + 1) & 1);

        const int j2 = 2 * jo + grp;  // this group's sub-tile
        const uint32_t sb = uS + (jo & 1) * 32768 + grp * 16384;

        // ---- Q fragments (re-ldsm per super-stage; transient regs) ----
        uint32_t fq[2][4][4];
        {
            const int row = wq * 16 + (l & 15);
#pragma unroll
            for (int sp = 0; sp < 2; sp++)
#pragma unroll
                for (int ks = 0; ks < 4; ks++) {
                    const int cb = (ks * 16 + (l >> 4) * 8) * 2;
                    ldsm4(fq[sp][ks], uQ + sp * 8192 + SWZ(row, row * 128 + cb));
                }
        }

        // ---- S = Q . K^T (64 q x 32 k) ----
        float s[4][4];
#pragma unroll
        for (int i = 0; i < 4; i++)
#pragma unroll
            for (int r = 0; r < 4; r++) s[i][r] = 0.f;

        const int nrow = (l & 7) + 8 * (l >> 4);
#pragma unroll
        for (int ks = 0; ks < 4; ks++) {
            uint32_t fk[2][2][4];
            const int cb = (ks * 16 + 8 * ((l >> 3) & 1)) * 2;
#pragma unroll
            for (int sp = 0; sp < 2; sp++)
#pragma unroll
                for (int g = 0; g < 2; g++) {
                    const int rr = g * 16 + nrow;
                    ldsm4(fk[sp][g], sb + sp * 4096 + SWZ(rr, rr * 128 + cb));
                }
#pragma unroll
            for (int nt = 0; nt < 4; nt++) {
                const int g = nt >> 1, i2 = (nt & 1) * 2;
                mma16816(s[nt], fq[0][ks], fk[0][g][i2], fk[0][g][i2 + 1]);
                mma16816(s[nt], fq[0][ks], fk[1][g][i2], fk[1][g][i2 + 1]);
                mma16816(s[nt], fq[1][ks], fk[0][g][i2], fk[0][g][i2 + 1]);
            }
        }

        // ---- ReLU + causal mask + split into P fragments ----
        uint32_t ph[2][4], pl[2][4];
        const bool nm = (j2 * 32 + 31 > qt * 64 + wq * 16);
#pragma unroll
        for (int nt = 0; nt < 4; nt++) {
            const int colg = j2 * 32 + nt * 8 + 2 * (l & 3);
            float v0 = fmaxf(s[nt][0], 0.f);
            float v1 = fmaxf(s[nt][1], 0.f);
            float v2 = fmaxf(s[nt][2], 0.f);
            float v3 = fmaxf(s[nt][3], 0.f);
            if (nm) {
                if (colg     > rowg)     v0 = 0.f;
                if (colg + 1 > rowg)     v1 = 0.f;
                if (colg     > rowg + 8) v2 = 0.f;
                if (colg + 1 > rowg + 8) v3 = 0.f;
            }
            const int js = nt >> 1, pos = (nt & 1) * 2;
            split_pack(v0, v1, ph[js][pos],     pl[js][pos]);
            split_pack(v2, v3, ph[js][pos + 1], pl[js][pos + 1]);
        }

        // ---- O += P . V (k=32) ----
#pragma unroll
        for (int js = 0; js < 2; js++) {
            uint32_t fv[2][4][4];
            const int vrow = js * 16 + (l & 15);
#pragma unroll
            for (int sp = 0; sp < 2; sp++)
#pragma unroll
                for (int g = 0; g < 4; g++) {
                    const int cb = (g * 16 + (l >> 4) * 8) * 2;
                    ldsm4t(fv[sp][g], sb + 8192 + sp * 4096 + SWZ(vrow, vrow * 128 + cb));
                }
#pragma unroll
            for (int dt = 0; dt < 8; dt++) {
                const int g = dt >> 1, i2 = (dt & 1) * 2;
                mma16816(o[dt], ph[js], fv[0][g][i2], fv[0][g][i2 + 1]);
                mma16816(o[dt], ph[js], fv[1][g][i2], fv[1][g][i2 + 1]);
                mma16816(o[dt], pl[js], fv[0][g][i2], fv[0][g][i2 + 1]);
            }
        }
    }

    // ---- merge group B partials into group A, then store ----
    __syncthreads();                 // ring no longer needed
    float* red = (float*)smd;        // [32 elems][128 threads], conflict-free
    const int t = wq * 32 + l;       // 0..127 (same for paired warps w, w+4)
    if (grp == 1) {
#pragma unroll
        for (int dt = 0; dt < 8; dt++)
#pragma unroll
            for (int r = 0; r < 4; r++)
                red[(dt * 4 + r) * 128 + t] = o[dt][r];
    }
    __syncthreads();
    if (grp == 0) {
#pragma unroll
        for (int dt = 0; dt < 8; dt++)
#pragma unroll
            for (int r = 0; r < 4; r++)
                o[dt][r] += red[(dt * 4 + r) * 128 + t];

#pragma unroll
        for (int dt = 0; dt < 8; dt++) {
            const int col = h * DH + dt * 8 + 2 * (l & 3);
            *(float2*)&out[((size_t)b * Tt + rowg) * Cc + col]     = make_float2(o[dt][0], o[dt][1]);
            *(float2*)&out[((size_t)b * Tt + rowg + 8) * Cc + col] = make_float2(o[dt][2], o[dt][3]);
        }
    }
}

// ---------------------------------------------------------------------------
extern "C" void kernel_launch(void* const* d_in, const int* in_sizes, int n_in,
                              void* d_out, int out_size)
{
    const float* x    = (const float*)d_in[0];
    const float* W    = (const float*)d_in[1];
    const float* bias = (const float*)d_in[2];
    float* out        = (float*)d_out;
    (void)in_sizes; (void)n_in; (void)out_size;

    // Unlock dynamic smem (idempotent; not a stream operation).
    cudaFuncSetAttribute(qkv_mma,  cudaFuncAttributeMaxDynamicSharedMemorySize, 65536);
    cudaFuncSetAttribute(attn_mma, cudaFuncAttributeMaxDynamicSharedMemorySize, 81920);

    cvt_x<<<dim3(Mm / 64, Cc / 64), 256>>>(x);
    cvt_w<<<(Cc * N3) / 1024, 256>>>(W);

    dim3 g1(N3 / 128, Mm / 128);    // (18, 64)
    qkv_mma<<<g1, 128, 65536>>>(bias);

    dim3 g2(Tt / 64, Hh, Bb);       // (32, 12, 4)
    attn_mma<<<g2, 256, 81920>>>(out);
}

// round 13
// speedup vs baseline: 1.1684x; 1.1684x over previous
#include <cuda_runtime.h>
#include <cuda_bf16.h>
#include <cuda_fp16.h>
#include <cstdint>

// Problem constants (fixed by setup_inputs)
#define Bb 4
#define Tt 2048
#define Cc 768
#define Hh 12
#define DH 64
#define Mm (Bb * Tt)      // 8192
#define N3 (3 * Cc)       // 2304
#define NKSTEP (Cc / 16)  // 48

// ---------------------------------------------------------------------------
// Device scratch.
// GEMM1 inputs: bf16 hi/lo splits (x TRANSPOSED [K][M], W natural [K][N]).
// Attention operands: Q fp16 hi/lo; K,V single fp16. All [B,H,T,D].
// ---------------------------------------------------------------------------
__device__ __nv_bfloat16 g_xh[(size_t)Cc * Mm], g_xl[(size_t)Cc * Mm];
__device__ __nv_bfloat16 g_wh[(size_t)Cc * N3], g_wl[(size_t)Cc * N3];
__device__ __half g_qh[(size_t)Bb * Hh * Tt * DH], g_ql[(size_t)Bb * Hh * Tt * DH];
__device__ __half g_k [(size_t)Bb * Hh * Tt * DH];
__device__ __half g_v [(size_t)Bb * Hh * Tt * DH];

// ---------------------------------------------------------------------------
// Helpers
// ---------------------------------------------------------------------------
__device__ __forceinline__ uint32_t smem_u32(const void* p) {
    uint32_t a;
    asm("{ .reg .u64 t; cvta.to.shared.u64 t, %1; cvt.u32.u64 %0, t; }"
        : "=r"(a) : "l"(p));
    return a;
}
__device__ __forceinline__ void ldsm4(uint32_t r[4], uint32_t a) {
    asm volatile("ldmatrix.sync.aligned.m8n8.x4.shared.b16 {%0,%1,%2,%3}, [%4];"
                 : "=r"(r[0]), "=r"(r[1]), "=r"(r[2]), "=r"(r[3]) : "r"(a));
}
__device__ __forceinline__ void ldsm4t(uint32_t r[4], uint32_t a) {
    asm volatile("ldmatrix.sync.aligned.m8n8.x4.trans.shared.b16 {%0,%1,%2,%3}, [%4];"
                 : "=r"(r[0]), "=r"(r[1]), "=r"(r[2]), "=r"(r[3]) : "r"(a));
}
// bf16 mma (GEMM1)
__device__ __forceinline__ void mma16816(float* c, const uint32_t* a, uint32_t b0, uint32_t b1) {
    asm volatile(
        "mma.sync.aligned.m16n8k16.row.col.f32.bf16.bf16.f32 "
        "{%0,%1,%2,%3}, {%4,%5,%6,%7}, {%8,%9}, {%0,%1,%2,%3};"
        : "+f"(c[0]), "+f"(c[1]), "+f"(c[2]), "+f"(c[3])
        : "r"(a[0]), "r"(a[1]), "r"(a[2]), "r"(a[3]), "r"(b0), "r"(b1));
}
// fp16 mma (attention)
__device__ __forceinline__ void mma16816h(float* c, const uint32_t* a, uint32_t b0, uint32_t b1) {
    asm volatile(
        "mma.sync.aligned.m16n8k16.row.col.f32.f16.f16.f32 "
        "{%0,%1,%2,%3}, {%4,%5,%6,%7}, {%8,%9}, {%0,%1,%2,%3};"
        : "+f"(c[0]), "+f"(c[1]), "+f"(c[2]), "+f"(c[3])
        : "r"(a[0]), "r"(a[1]), "r"(a[2]), "r"(a[3]), "r"(b0), "r"(b1));
}
// Fast bf16x3 split (GEMM1 inputs): packed cvt; hi halves via bit ops.
__device__ __forceinline__ void split_pack(float x0, float x1, uint32_t& hi, uint32_t& lo) {
    uint32_t h;
    asm("cvt.rn.bf16x2.f32 %0, %1, %2;" : "=r"(h) : "f"(x1), "f"(x0));
    const float h0 = __uint_as_float(h << 16);
    const float h1 = __uint_as_float(h & 0xFFFF0000u);
    uint32_t lw;
    asm("cvt.rn.bf16x2.f32 %0, %1, %2;" : "=r"(lw) : "f"(x1 - h1), "f"(x0 - h0));
    hi = h; lo = lw;
}
// fp16 pack / hi-lo split
__device__ __forceinline__ uint32_t packh2(float x0, float x1) {
    uint32_t h;
    asm("cvt.rn.f16x2.f32 %0, %1, %2;" : "=r"(h) : "f"(x1), "f"(x0));
    return h;   // low halfword = x0
}
__device__ __forceinline__ void splith(float x0, float x1, uint32_t& hi, uint32_t& lo) {
    hi = packh2(x0, x1);
    const __half2 t = *(const __half2*)&hi;
    lo = packh2(x0 - __low2float(t), x1 - __high2float(t));
}

#define CP16(s, g) \
    asm volatile("cp.async.cg.shared.global [%0], [%1], 16;" :: "r"(s), "l"(g))
#define CP_COMMIT() asm volatile("cp.async.commit_group;" ::: "memory")
#define CP_WAIT0()  asm volatile("cp.async.wait_group 0;" ::: "memory")

#define SWZ(row, byteoff) ((byteoff) ^ (((row) & 7) << 4))

// ---------------------------------------------------------------------------
// cvt_x: fp32 x[M][K] -> bf16 hi/lo TRANSPOSED [K][M]  (unchanged)
// ---------------------------------------------------------------------------
__global__ __launch_bounds__(256) void cvt_x(const float* __restrict__ x) {
    __shared__ float S[64][65];
    const int m0 = blockIdx.x * 64, k0 = blockIdx.y * 64;
    const int tid = threadIdx.x;
#pragma unroll
    for (int i = 0; i < 4; i++) {
        const int c = tid + i * 256;
        const int row = c >> 4;
        const int c4 = (c & 15) * 4;
        float4 v = *(const float4*)&x[(size_t)(m0 + row) * Cc + k0 + c4];
        S[row][c4] = v.x; S[row][c4 + 1] = v.y; S[row][c4 + 2] = v.z; S[row][c4 + 3] = v.w;
    }
    __syncthreads();
#pragma unroll
    for (int i = 0; i < 2; i++) {
        const int c = tid + i * 256;
        const int k = c >> 3;
        const int mc = c & 7;
        uint32_t hw[4], lw[4];
#pragma unroll
        for (int e = 0; e < 4; e++)
            split_pack(S[mc * 8 + 2 * e][k], S[mc * 8 + 2 * e + 1][k], hw[e], lw[e]);
        const size_t g = (size_t)(k0 + k) * Mm + m0 + mc * 8;
        *(uint4*)&g_xh[g] = make_uint4(hw[0], hw[1], hw[2], hw[3]);
        *(uint4*)&g_xl[g] = make_uint4(lw[0], lw[1], lw[2], lw[3]);
    }
}
__global__ __launch_bounds__(256) void cvt_w(const float* __restrict__ W) {
    const size_t base = ((size_t)blockIdx.x * 256 + threadIdx.x) * 4;
    float4 v = *(const float4*)&W[base];
    uint32_t h01, l01, h23, l23;
    split_pack(v.x, v.y, h01, l01);
    split_pack(v.z, v.w, h23, l23);
    *(uint2*)&g_wh[base] = make_uint2(h01, h23);
    *(uint2*)&g_wl[base] = make_uint2(l01, l23);
}

// ---------------------------------------------------------------------------
// Kernel 1: qkv = x @ W + b via mma.sync bf16x3 (R9 mainloop).
// Epilogue now emits fp16: Q as hi/lo pair (scale folded), K/V single fp16.
// ---------------------------------------------------------------------------
__global__ __launch_bounds__(128) void qkv_mma(const float* __restrict__ bias) {
    extern __shared__ __align__(128) uint8_t smd[];
    const uint32_t uS = smem_u32(smd);

    const int tid = threadIdx.x;
    const int l   = tid & 31;
    const int w   = tid >> 5;
    const int wm  = w >> 1;
    const int wn  = w & 1;
    const int m0  = blockIdx.y * 128;
    const int n0  = blockIdx.x * 128;

    float acc[4][8][4];
#pragma unroll
    for (int i = 0; i < 4; i++)
#pragma unroll
        for (int j = 0; j < 8; j++)
#pragma unroll
            for (int r = 0; r < 4; r++) acc[i][j][r] = 0.f;

    const int cr = tid >> 3;
    const int cc = (tid & 7) * 2;
    const uint32_t so0 = (uint32_t)SWZ(cr, cr * 256 + cc * 16);
    const uint32_t so1 = (uint32_t)SWZ(cr, cr * 256 + cc * 16 + 16);

#define QKV_SUB(kb, bofs) do {                                                \
    const int _k = (kb) * 16 + cr;                                            \
    const uint32_t _b = uS + (bofs);                                          \
    const size_t _ga = (size_t)_k * Mm + m0 + cc * 8;                         \
    const size_t _gb = (size_t)_k * N3 + n0 + cc * 8;                         \
    CP16(_b + so0,         g_xh + _ga);                                       \
    CP16(_b + so1,         g_xh + _ga + 8);                                   \
    CP16(_b + 4096 + so0,  g_xl + _ga);                                       \
    CP16(_b + 4096 + so1,  g_xl + _ga + 8);                                   \
    CP16(_b + 8192 + so0,  g_wh + _gb);                                       \
    CP16(_b + 8192 + so1,  g_wh + _gb + 8);                                   \
    CP16(_b + 12288 + so0, g_wl + _gb);                                       \
    CP16(_b + 12288 + so1, g_wl + _gb + 8);                                   \
} while (0)

#define QKV_ISSUE2(kb, sst) do {                                              \
    QKV_SUB(kb, (sst) * 32768);                                               \
    QKV_SUB((kb) + 1, (sst) * 32768 + 16384);                                 \
    CP_COMMIT();                                                              \
} while (0)

    const int arow = (l & 7) + 8 * (l >> 4);
    const int abyt = wm * 128 + ((l >> 3) & 1) * 16;
    const int brow = (l & 15);
    const int bbyt = wn * 128 + (l >> 4) * 16;

    QKV_ISSUE2(0, 0);

    for (int kb2 = 0; kb2 < NKSTEP / 2; kb2++) {       // 24 rounds
        CP_WAIT0();
        __syncthreads();
        if (kb2 + 1 < NKSTEP / 2) QKV_ISSUE2(2 * (kb2 + 1), (kb2 + 1) & 1);

        const uint32_t superb = uS + (kb2 & 1) * 32768;
#pragma unroll
        for (int sub = 0; sub < 2; sub++) {
            const uint32_t sb = superb + sub * 16384;
            uint32_t fa[2][4][4], fb[2][4][4];
#pragma unroll
            for (int sp = 0; sp < 2; sp++) {
#pragma unroll
                for (int mt = 0; mt < 4; mt++)
                    ldsm4t(fa[sp][mt], sb + sp * 4096 + SWZ(arow, arow * 256 + abyt + mt * 32));
#pragma unroll
                for (int g = 0; g < 4; g++)
                    ldsm4t(fb[sp][g], sb + 8192 + sp * 4096 + SWZ(brow, brow * 256 + bbyt + g * 32));
            }

#pragma unroll
            for (int mt = 0; mt < 4; mt++)
#pragma unroll
                for (int nt = 0; nt < 8; nt++) {
                    const int g = nt >> 1, i2 = (nt & 1) * 2;
                    mma16816(acc[mt][nt], fa[0][mt], fb[0][g][i2], fb[0][g][i2 + 1]);
                    mma16816(acc[mt][nt], fa[0][mt], fb[1][g][i2], fb[1][g][i2 + 1]);
                    mma16816(acc[mt][nt], fa[1][mt], fb[0][g][i2], fb[0][g][i2 + 1]);
                }
        }
    }

    // ---- Epilogue (fp16 outputs) ----
    const int which = n0 / Cc;                  // 0=Q,1=K,2=V
    const int nloc0 = n0 - which * Cc;
    const int mrow = m0 + wm * 64 + (l >> 2);
    const int b_   = mrow >> 11;

#pragma unroll
    for (int mt = 0; mt < 4; mt++) {
        const int t1 = (mrow + mt * 16) & (Tt - 1);
#pragma unroll
        for (int nt = 0; nt < 8; nt++) {
            const int n  = nloc0 + wn * 64 + nt * 8 + 2 * (l & 3);
            const int hh = n >> 6;
            const int d  = n & 63;
            const float b0 = bias[which * Cc + n];
            const float b1 = bias[which * Cc + n + 1];
            const size_t i1 = (((size_t)b_ * Hh + hh) * Tt + t1) * DH + d;
            const size_t i2 = i1 + (size_t)8 * DH;
            if (which == 0) {
                uint32_t h01, l01, h23, l23;
                splith((acc[mt][nt][0] + b0) * 0.125f, (acc[mt][nt][1] + b1) * 0.125f, h01, l01);
                splith((acc[mt][nt][2] + b0) * 0.125f, (acc[mt][nt][3] + b1) * 0.125f, h23, l23);
                *(uint32_t*)&g_qh[i1] = h01;  *(uint32_t*)&g_ql[i1] = l01;
                *(uint32_t*)&g_qh[i2] = h23;  *(uint32_t*)&g_ql[i2] = l23;
            } else {
                __half* dst = (which == 1) ? g_k : g_v;
                *(uint32_t*)&dst[i1] = packh2(acc[mt][nt][0] + b0, acc[mt][nt][1] + b1);
                *(uint32_t*)&dst[i2] = packh2(acc[mt][nt][2] + b0, acc[mt][nt][3] + b1);
            }
        }
    }
}

// ---------------------------------------------------------------------------
// Kernel 2: causal ReLU attention, fp16 2-term. BQ=64, BK=64 per sync round.
// Static 32KB smem: 2 super-stages x 16KB; each super-stage = 2 sub-tiles
// (8KB: K 4KB @0, V 4KB @4096). Q fragments (hi/lo fp16) via direct LDG.
// Phase-interleaved: S(0);S(1); split(0);PV(0); split(1);PV(1).
// ---------------------------------------------------------------------------
__global__ __launch_bounds__(128) void attn_mma(float* __restrict__ out)
{
    __shared__ __align__(128) uint8_t sm[32768];
    const uint32_t uS = smem_u32(sm);

    const int tid = threadIdx.x;
    const int l   = tid & 31;
    const int w   = tid >> 5;
    const int qt  = (gridDim.x - 1) - blockIdx.x;    // 0..31, long first
    const int h   = blockIdx.y;
    const int b   = blockIdx.z;

    const size_t hb = ((size_t)b * Hh + h) * (size_t)Tt * DH;

#define ATT_ISSUE2(j64, sst) do {                                           \
    const uint32_t _sb = uS + (sst) * 16384;                                \
    _Pragma("unroll")                                                       \
    for (int _i = 0; _i < 4; _i++) {                                        \
        const int _c = tid + _i * 128;       /* 0..511 */                   \
        const int _row = _c >> 3;            /* 0..63  */                   \
        const int _c16 = _c & 7;                                            \
        const int _sr  = _row & 31;                                         \
        const uint32_t _so = ((_row & 32) ? 8192u : 0u)                     \
                           + SWZ(_sr, _sr * 128 + _c16 * 16);               \
        const size_t _g = hb + (size_t)((j64) * 64 + _row) * DH + _c16 * 8; \
        CP16(_sb + _so,        g_k + _g);                                   \
        CP16(_sb + 4096 + _so, g_v + _g);                                   \
    }                                                                       \
    CP_COMMIT();                                                            \
} while (0)

    ATT_ISSUE2(0, 0);                 // first 64 kv rows -> super-stage 0

    // Q fragments via direct LDG (fp16 hi/lo; matches mma A-fragment layout)
    uint32_t fq[2][4][4];
    const int r0 = qt * 64 + w * 16 + (l >> 2);
    {
        const size_t qb0 = hb + (size_t)r0 * DH;
        const size_t qb1 = qb0 + (size_t)8 * DH;
#pragma unroll
        for (int ks = 0; ks < 4; ks++) {
            const int c0 = ks * 16 + (l & 3) * 2;
            fq[0][ks][0] = *(const uint32_t*)&g_qh[qb0 + c0];
            fq[0][ks][1] = *(const uint32_t*)&g_qh[qb1 + c0];
            fq[0][ks][2] = *(const uint32_t*)&g_qh[qb0 + c0 + 8];
            fq[0][ks][3] = *(const uint32_t*)&g_qh[qb1 + c0 + 8];
            fq[1][ks][0] = *(const uint32_t*)&g_ql[qb0 + c0];
            fq[1][ks][1] = *(const uint32_t*)&g_ql[qb1 + c0];
            fq[1][ks][2] = *(const uint32_t*)&g_ql[qb0 + c0 + 8];
            fq[1][ks][3] = *(const uint32_t*)&g_ql[qb1 + c0 + 8];
        }
    }

    float o[8][4];
#pragma unroll
    for (int i = 0; i < 8; i++)
#pragma unroll
        for (int r = 0; r < 4; r++) o[i][r] = 0.f;

    const int rowg = r0;

    for (int jo = 0; jo <= qt; jo++) {
        CP_WAIT0();
        __syncthreads();
        if (jo < qt) ATT_ISSUE2(jo + 1, (jo + 1) & 1);

        const uint32_t superb = uS + (jo & 1) * 16384;

        // ===== Phase A: S for BOTH sub-tiles =====
        float s[2][4][4];
#pragma unroll
        for (int sub = 0; sub < 2; sub++)
#pragma unroll
            for (int i = 0; i < 4; i++)
#pragma unroll
                for (int r = 0; r < 4; r++) s[sub][i][r] = 0.f;

        const int nrow = (l & 7) + 8 * (l >> 4);
#pragma unroll
        for (int sub = 0; sub < 2; sub++) {
            const uint32_t sb = superb + sub * 8192;
#pragma unroll
            for (int ks = 0; ks < 4; ks++) {
                uint32_t fk[2][4];
                const int cb = (ks * 16 + 8 * ((l >> 3) & 1)) * 2;
#pragma unroll
                for (int g = 0; g < 2; g++) {
                    const int rr = g * 16 + nrow;
                    ldsm4(fk[g], sb + SWZ(rr, rr * 128 + cb));
                }
#pragma unroll
                for (int nt = 0; nt < 4; nt++) {
                    const int g = nt >> 1, i2 = (nt & 1) * 2;
                    mma16816h(s[sub][nt], fq[0][ks], fk[g][i2], fk[g][i2 + 1]);
                    mma16816h(s[sub][nt], fq[1][ks], fk[g][i2], fk[g][i2 + 1]);
                }
            }
        }

        // ===== Phase B: split + PV per sub-tile =====
#pragma unroll
        for (int sub = 0; sub < 2; sub++) {
            const int j2 = 2 * jo + sub;
            const uint32_t sb = superb + sub * 8192;

            uint32_t ph[2][4], pl[2][4];
            const bool nm = (j2 * 32 + 31 > qt * 64 + w * 16);
#pragma unroll
            for (int nt = 0; nt < 4; nt++) {
                const int colg = j2 * 32 + nt * 8 + 2 * (l & 3);
                float v0 = fmaxf(s[sub][nt][0], 0.f);
                float v1 = fmaxf(s[sub][nt][1], 0.f);
                float v2 = fmaxf(s[sub][nt][2], 0.f);
                float v3 = fmaxf(s[sub][nt][3], 0.f);
                if (nm) {
                    if (colg     > rowg)     v0 = 0.f;
                    if (colg + 1 > rowg)     v1 = 0.f;
                    if (colg     > rowg + 8) v2 = 0.f;
                    if (colg + 1 > rowg + 8) v3 = 0.f;
                }
                const int js = nt >> 1, pos = (nt & 1) * 2;
                splith(v0, v1, ph[js][pos],     pl[js][pos]);
                splith(v2, v3, ph[js][pos + 1], pl[js][pos + 1]);
            }

#pragma unroll
            for (int js = 0; js < 2; js++) {
                uint32_t fv[4][4];
                const int vrow = js * 16 + (l & 15);
#pragma unroll
                for (int g = 0; g < 4; g++) {
                    const int cb = (g * 16 + (l >> 4) * 8) * 2;
                    ldsm4t(fv[g], sb + 4096 + SWZ(vrow, vrow * 128 + cb));
                }
#pragma unroll
                for (int dt = 0; dt < 8; dt++) {
                    const int g = dt >> 1, i2 = (dt & 1) * 2;
                    mma16816h(o[dt], ph[js], fv[g][i2], fv[g][i2 + 1]);
                    mma16816h(o[dt], pl[js], fv[g][i2], fv[g][i2 + 1]);
                }
            }
        }
    }

    // ---- store O ----
#pragma unroll
    for (int dt = 0; dt < 8; dt++) {
        const int col = h * DH + dt * 8 + 2 * (l & 3);
        *(float2*)&out[((size_t)b * Tt + rowg) * Cc + col]     = make_float2(o[dt][0], o[dt][1]);
        *(float2*)&out[((size_t)b * Tt + rowg + 8) * Cc + col] = make_float2(o[dt][2], o[dt][3]);
    }
}

// ---------------------------------------------------------------------------
extern "C" void kernel_launch(void* const* d_in, const int* in_sizes, int n_in,
                              void* d_out, int out_size)
{
    const float* x    = (const float*)d_in[0];
    const float* W    = (const float*)d_in[1];
    const float* bias = (const float*)d_in[2];
    float* out        = (float*)d_out;
    (void)in_sizes; (void)n_in; (void)out_size;

    // Unlock 64KB dynamic smem for qkv (idempotent; not a stream operation).
    cudaFuncSetAttribute(qkv_mma, cudaFuncAttributeMaxDynamicSharedMemorySize, 65536);

    cvt_x<<<dim3(Mm / 64, Cc / 64), 256>>>(x);
    cvt_w<<<(Cc * N3) / 1024, 256>>>(W);

    dim3 g1(N3 / 128, Mm / 128);    // (18, 64)
    qkv_mma<<<g1, 128, 65536>>>(bias);

    dim3 g2(Tt / 64, Hh, Bb);       // (32, 12, 4)
    attn_mma<<<g2, 128>>>(out);
}

// round 14
// speedup vs baseline: 1.3488x; 1.1545x over previous
#include <cuda_runtime.h>
#include <cuda_bf16.h>
#include <cuda_fp16.h>
#include <cstdint>

// Problem constants (fixed by setup_inputs)
#define Bb 4
#define Tt 2048
#define Cc 768
#define Hh 12
#define DH 64
#define Mm (Bb * Tt)      // 8192
#define N3 (3 * Cc)       // 2304
#define NKSTEP (Cc / 16)  // 48

// ---------------------------------------------------------------------------
// Device scratch (all fp16 now).
// x: hi/lo fp16 TRANSPOSED [K][M]. W: single fp16 [K][N].
// Q: fp16 hi/lo; K,V: single fp16. All attention operands [B,H,T,D].
// ---------------------------------------------------------------------------
__device__ __half g_xh[(size_t)Cc * Mm], g_xl[(size_t)Cc * Mm];
__device__ __half g_w [(size_t)Cc * N3];
__device__ __half g_qh[(size_t)Bb * Hh * Tt * DH], g_ql[(size_t)Bb * Hh * Tt * DH];
__device__ __half g_k [(size_t)Bb * Hh * Tt * DH];
__device__ __half g_v [(size_t)Bb * Hh * Tt * DH];

// ---------------------------------------------------------------------------
// Helpers
// ---------------------------------------------------------------------------
__device__ __forceinline__ uint32_t smem_u32(const void* p) {
    uint32_t a;
    asm("{ .reg .u64 t; cvta.to.shared.u64 t, %1; cvt.u32.u64 %0, t; }"
        : "=r"(a) : "l"(p));
    return a;
}
__device__ __forceinline__ void ldsm4(uint32_t r[4], uint32_t a) {
    asm volatile("ldmatrix.sync.aligned.m8n8.x4.shared.b16 {%0,%1,%2,%3}, [%4];"
                 : "=r"(r[0]), "=r"(r[1]), "=r"(r[2]), "=r"(r[3]) : "r"(a));
}
__device__ __forceinline__ void ldsm4t(uint32_t r[4], uint32_t a) {
    asm volatile("ldmatrix.sync.aligned.m8n8.x4.trans.shared.b16 {%0,%1,%2,%3}, [%4];"
                 : "=r"(r[0]), "=r"(r[1]), "=r"(r[2]), "=r"(r[3]) : "r"(a));
}
// fp16 mma, fp32 accum
__device__ __forceinline__ void mma16816h(float* c, const uint32_t* a, uint32_t b0, uint32_t b1) {
    asm volatile(
        "mma.sync.aligned.m16n8k16.row.col.f32.f16.f16.f32 "
        "{%0,%1,%2,%3}, {%4,%5,%6,%7}, {%8,%9}, {%0,%1,%2,%3};"
        : "+f"(c[0]), "+f"(c[1]), "+f"(c[2]), "+f"(c[3])
        : "r"(a[0]), "r"(a[1]), "r"(a[2]), "r"(a[3]), "r"(b0), "r"(b1));
}
// fp16 pack / hi-lo split
__device__ __forceinline__ uint32_t packh2(float x0, float x1) {
    uint32_t h;
    asm("cvt.rn.f16x2.f32 %0, %1, %2;" : "=r"(h) : "f"(x1), "f"(x0));
    return h;   // low halfword = x0
}
__device__ __forceinline__ void splith(float x0, float x1, uint32_t& hi, uint32_t& lo) {
    hi = packh2(x0, x1);
    const __half2 t = *(const __half2*)&hi;
    lo = packh2(x0 - __low2float(t), x1 - __high2float(t));
}

#define CP16(s, g) \
    asm volatile("cp.async.cg.shared.global [%0], [%1], 16;" :: "r"(s), "l"(g))
#define CP_COMMIT() asm volatile("cp.async.commit_group;" ::: "memory")
#define CP_WAIT0()  asm volatile("cp.async.wait_group 0;" ::: "memory")

#define SWZ(row, byteoff) ((byteoff) ^ (((row) & 7) << 4))

// ---------------------------------------------------------------------------
// cvt_x: fp32 x[M][K] -> fp16 hi/lo TRANSPOSED [K][M]
// ---------------------------------------------------------------------------
__global__ __launch_bounds__(256) void cvt_x(const float* __restrict__ x) {
    __shared__ float S[64][65];
    const int m0 = blockIdx.x * 64, k0 = blockIdx.y * 64;
    const int tid = threadIdx.x;
#pragma unroll
    for (int i = 0; i < 4; i++) {
        const int c = tid + i * 256;
        const int row = c >> 4;
        const int c4 = (c & 15) * 4;
        float4 v = *(const float4*)&x[(size_t)(m0 + row) * Cc + k0 + c4];
        S[row][c4] = v.x; S[row][c4 + 1] = v.y; S[row][c4 + 2] = v.z; S[row][c4 + 3] = v.w;
    }
    __syncthreads();
#pragma unroll
    for (int i = 0; i < 2; i++) {
        const int c = tid + i * 256;
        const int k = c >> 3;
        const int mc = c & 7;
        uint32_t hw[4], lw[4];
#pragma unroll
        for (int e = 0; e < 4; e++)
            splith(S[mc * 8 + 2 * e][k], S[mc * 8 + 2 * e + 1][k], hw[e], lw[e]);
        const size_t g = (size_t)(k0 + k) * Mm + m0 + mc * 8;
        *(uint4*)&g_xh[g] = make_uint4(hw[0], hw[1], hw[2], hw[3]);
        *(uint4*)&g_xl[g] = make_uint4(lw[0], lw[1], lw[2], lw[3]);
    }
}
// cvt_w: fp32 W[K][N] -> single fp16
__global__ __launch_bounds__(256) void cvt_w(const float* __restrict__ W) {
    const size_t base = ((size_t)blockIdx.x * 256 + threadIdx.x) * 4;
    float4 v = *(const float4*)&W[base];
    *(uint2*)&g_w[base] = make_uint2(packh2(v.x, v.y), packh2(v.z, v.w));
}

// ---------------------------------------------------------------------------
// Kernel 1: qkv = x @ W + b via fp16 2-term mma (xh*W + xl*W).
// 128x128 block, 128 thr, 4 warps (2m x 2n), warp 64x64.
// 48KB STATIC smem: 2 super-stages x 24KB; each = 2 sub-stages of 12KB
// (A_hi @0, A_lo @4096, B @8192). Two k-steps per wait+sync.
// ---------------------------------------------------------------------------
__global__ __launch_bounds__(128) void qkv_mma(const float* __restrict__ bias) {
    __shared__ __align__(128) uint8_t smd[49152];
    const uint32_t uS = smem_u32(smd);

    const int tid = threadIdx.x;
    const int l   = tid & 31;
    const int w   = tid >> 5;
    const int wm  = w >> 1;
    const int wn  = w & 1;
    const int m0  = blockIdx.y * 128;
    const int n0  = blockIdx.x * 128;

    float acc[4][8][4];
#pragma unroll
    for (int i = 0; i < 4; i++)
#pragma unroll
        for (int j = 0; j < 8; j++)
#pragma unroll
            for (int r = 0; r < 4; r++) acc[i][j][r] = 0.f;

    const int cr = tid >> 3;
    const int cc = (tid & 7) * 2;
    const uint32_t so0 = (uint32_t)SWZ(cr, cr * 256 + cc * 16);
    const uint32_t so1 = (uint32_t)SWZ(cr, cr * 256 + cc * 16 + 16);

#define QKV_SUB(kb, bofs) do {                                                \
    const int _k = (kb) * 16 + cr;                                            \
    const uint32_t _b = uS + (bofs);                                          \
    const size_t _ga = (size_t)_k * Mm + m0 + cc * 8;                         \
    const size_t _gb = (size_t)_k * N3 + n0 + cc * 8;                         \
    CP16(_b + so0,        g_xh + _ga);                                        \
    CP16(_b + so1,        g_xh + _ga + 8);                                    \
    CP16(_b + 4096 + so0, g_xl + _ga);                                        \
    CP16(_b + 4096 + so1, g_xl + _ga + 8);                                    \
    CP16(_b + 8192 + so0, g_w + _gb);                                         \
    CP16(_b + 8192 + so1, g_w + _gb + 8);                                     \
} while (0)

#define QKV_ISSUE2(kb, sst) do {                                              \
    QKV_SUB(kb, (sst) * 24576);                                               \
    QKV_SUB((kb) + 1, (sst) * 24576 + 12288);                                 \
    CP_COMMIT();                                                              \
} while (0)

    const int arow = (l & 7) + 8 * (l >> 4);
    const int abyt = wm * 128 + ((l >> 3) & 1) * 16;
    const int brow = (l & 15);
    const int bbyt = wn * 128 + (l >> 4) * 16;

    QKV_ISSUE2(0, 0);

    for (int kb2 = 0; kb2 < NKSTEP / 2; kb2++) {       // 24 rounds
        CP_WAIT0();
        __syncthreads();
        if (kb2 + 1 < NKSTEP / 2) QKV_ISSUE2(2 * (kb2 + 1), (kb2 + 1) & 1);

        const uint32_t superb = uS + (kb2 & 1) * 24576;
#pragma unroll
        for (int sub = 0; sub < 2; sub++) {
            const uint32_t sb = superb + sub * 12288;
            uint32_t fa[2][4][4], fb[4][4];
#pragma unroll
            for (int sp = 0; sp < 2; sp++)
#pragma unroll
                for (int mt = 0; mt < 4; mt++)
                    ldsm4t(fa[sp][mt], sb + sp * 4096 + SWZ(arow, arow * 256 + abyt + mt * 32));
#pragma unroll
            for (int g = 0; g < 4; g++)
                ldsm4t(fb[g], sb + 8192 + SWZ(brow, brow * 256 + bbyt + g * 32));

#pragma unroll
            for (int mt = 0; mt < 4; mt++)
#pragma unroll
                for (int nt = 0; nt < 8; nt++) {
                    const int g = nt >> 1, i2 = (nt & 1) * 2;
                    mma16816h(acc[mt][nt], fa[0][mt], fb[g][i2], fb[g][i2 + 1]);
                    mma16816h(acc[mt][nt], fa[1][mt], fb[g][i2], fb[g][i2 + 1]);
                }
        }
    }

    // ---- Epilogue (fp16 outputs) ----
    const int which = n0 / Cc;                  // 0=Q,1=K,2=V
    const int nloc0 = n0 - which * Cc;
    const int mrow = m0 + wm * 64 + (l >> 2);
    const int b_   = mrow >> 11;

#pragma unroll
    for (int mt = 0; mt < 4; mt++) {
        const int t1 = (mrow + mt * 16) & (Tt - 1);
#pragma unroll
        for (int nt = 0; nt < 8; nt++) {
            const int n  = nloc0 + wn * 64 + nt * 8 + 2 * (l & 3);
            const int hh = n >> 6;
            const int d  = n & 63;
            const float b0 = bias[which * Cc + n];
            const float b1 = bias[which * Cc + n + 1];
            const size_t i1 = (((size_t)b_ * Hh + hh) * Tt + t1) * DH + d;
            const size_t i2 = i1 + (size_t)8 * DH;
            if (which == 0) {
                uint32_t h01, l01, h23, l23;
                splith((acc[mt][nt][0] + b0) * 0.125f, (acc[mt][nt][1] + b1) * 0.125f, h01, l01);
                splith((acc[mt][nt][2] + b0) * 0.125f, (acc[mt][nt][3] + b1) * 0.125f, h23, l23);
                *(uint32_t*)&g_qh[i1] = h01;  *(uint32_t*)&g_ql[i1] = l01;
                *(uint32_t*)&g_qh[i2] = h23;  *(uint32_t*)&g_ql[i2] = l23;
            } else {
                __half* dst = (which == 1) ? g_k : g_v;
                *(uint32_t*)&dst[i1] = packh2(acc[mt][nt][0] + b0, acc[mt][nt][1] + b1);
                *(uint32_t*)&dst[i2] = packh2(acc[mt][nt][2] + b0, acc[mt][nt][3] + b1);
            }
        }
    }
}

// ---------------------------------------------------------------------------
// Kernel 2: causal ReLU attention (unchanged from R13). fp16 2-term.
// BQ=64, BK=64 per sync round. Static 32KB smem: 2 super-stages x 16KB;
// each = 2 sub-tiles (8KB: K 4KB @0, V 4KB @4096). Q via direct LDG.
// ---------------------------------------------------------------------------
__global__ __launch_bounds__(128) void attn_mma(float* __restrict__ out)
{
    __shared__ __align__(128) uint8_t sm[32768];
    const uint32_t uS = smem_u32(sm);

    const int tid = threadIdx.x;
    const int l   = tid & 31;
    const int w   = tid >> 5;
    const int qt  = (gridDim.x - 1) - blockIdx.x;    // 0..31, long first
    const int h   = blockIdx.y;
    const int b   = blockIdx.z;

    const size_t hb = ((size_t)b * Hh + h) * (size_t)Tt * DH;

#define ATT_ISSUE2(j64, sst) do {                                           \
    const uint32_t _sb = uS + (sst) * 16384;                                \
    _Pragma("unroll")                                                       \
    for (int _i = 0; _i < 4; _i++) {                                        \
        const int _c = tid + _i * 128;       /* 0..511 */                   \
        const int _row = _c >> 3;            /* 0..63  */                   \
        const int _c16 = _c & 7;                                            \
        const int _sr  = _row & 31;                                         \
        const uint32_t _so = ((_row & 32) ? 8192u : 0u)                     \
                           + SWZ(_sr, _sr * 128 + _c16 * 16);               \
        const size_t _g = hb + (size_t)((j64) * 64 + _row) * DH + _c16 * 8; \
        CP16(_sb + _so,        g_k + _g);                                   \
        CP16(_sb + 4096 + _so, g_v + _g);                                   \
    }                                                                       \
    CP_COMMIT();                                                            \
} while (0)

    ATT_ISSUE2(0, 0);                 // first 64 kv rows -> super-stage 0

    // Q fragments via direct LDG (fp16 hi/lo; matches mma A-fragment layout)
    uint32_t fq[2][4][4];
    const int r0 = qt * 64 + w * 16 + (l >> 2);
    {
        const size_t qb0 = hb + (size_t)r0 * DH;
        const size_t qb1 = qb0 + (size_t)8 * DH;
#pragma unroll
        for (int ks = 0; ks < 4; ks++) {
            const int c0 = ks * 16 + (l & 3) * 2;
            fq[0][ks][0] = *(const uint32_t*)&g_qh[qb0 + c0];
            fq[0][ks][1] = *(const uint32_t*)&g_qh[qb1 + c0];
            fq[0][ks][2] = *(const uint32_t*)&g_qh[qb0 + c0 + 8];
            fq[0][ks][3] = *(const uint32_t*)&g_qh[qb1 + c0 + 8];
            fq[1][ks][0] = *(const uint32_t*)&g_ql[qb0 + c0];
            fq[1][ks][1] = *(const uint32_t*)&g_ql[qb1 + c0];
            fq[1][ks][2] = *(const uint32_t*)&g_ql[qb0 + c0 + 8];
            fq[1][ks][3] = *(const uint32_t*)&g_ql[qb1 + c0 + 8];
        }
    }

    float o[8][4];
#pragma unroll
    for (int i = 0; i < 8; i++)
#pragma unroll
        for (int r = 0; r < 4; r++) o[i][r] = 0.f;

    const int rowg = r0;

    for (int jo = 0; jo <= qt; jo++) {
        CP_WAIT0();
        __syncthreads();
        if (jo < qt) ATT_ISSUE2(jo + 1, (jo + 1) & 1);

        const uint32_t superb = uS + (jo & 1) * 16384;

        // ===== Phase A: S for BOTH sub-tiles =====
        float s[2][4][4];
#pragma unroll
        for (int sub = 0; sub < 2; sub++)
#pragma unroll
            for (int i = 0; i < 4; i++)
#pragma unroll
                for (int r = 0; r < 4; r++) s[sub][i][r] = 0.f;

        const int nrow = (l & 7) + 8 * (l >> 4);
#pragma unroll
        for (int sub = 0; sub < 2; sub++) {
            const uint32_t sb = superb + sub * 8192;
#pragma unroll
            for (int ks = 0; ks < 4; ks++) {
                uint32_t fk[2][4];
                const int cb = (ks * 16 + 8 * ((l >> 3) & 1)) * 2;
#pragma unroll
                for (int g = 0; g < 2; g++) {
                    const int rr = g * 16 + nrow;
                    ldsm4(fk[g], sb + SWZ(rr, rr * 128 + cb));
                }
#pragma unroll
                for (int nt = 0; nt < 4; nt++) {
                    const int g = nt >> 1, i2 = (nt & 1) * 2;
                    mma16816h(s[sub][nt], fq[0][ks], fk[g][i2], fk[g][i2 + 1]);
                    mma16816h(s[sub][nt], fq[1][ks], fk[g][i2], fk[g][i2 + 1]);
                }
            }
        }

        // ===== Phase B: split + PV per sub-tile =====
#pragma unroll
        for (int sub = 0; sub < 2; sub++) {
            const int j2 = 2 * jo + sub;
            const uint32_t sb = superb + sub * 8192;

            uint32_t ph[2][4], pl[2][4];
            const bool nm = (j2 * 32 + 31 > qt * 64 + w * 16);
#pragma unroll
            for (int nt = 0; nt < 4; nt++) {
                const int colg = j2 * 32 + nt * 8 + 2 * (l & 3);
                float v0 = fmaxf(s[sub][nt][0], 0.f);
                float v1 = fmaxf(s[sub][nt][1], 0.f);
                float v2 = fmaxf(s[sub][nt][2], 0.f);
                float v3 = fmaxf(s[sub][nt][3], 0.f);
                if (nm) {
                    if (colg     > rowg)     v0 = 0.f;
                    if (colg + 1 > rowg)     v1 = 0.f;
                    if (colg     > rowg + 8) v2 = 0.f;
                    if (colg + 1 > rowg + 8) v3 = 0.f;
                }
                const int js = nt >> 1, pos = (nt & 1) * 2;
                splith(v0, v1, ph[js][pos],     pl[js][pos]);
                splith(v2, v3, ph[js][pos + 1], pl[js][pos + 1]);
            }

#pragma unroll
            for (int js = 0; js < 2; js++) {
                uint32_t fv[4][4];
                const int vrow = js * 16 + (l & 15);
#pragma unroll
                for (int g = 0; g < 4; g++) {
                    const int cb = (g * 16 + (l >> 4) * 8) * 2;
                    ldsm4t(fv[g], sb + 4096 + SWZ(vrow, vrow * 128 + cb));
                }
#pragma unroll
                for (int dt = 0; dt < 8; dt++) {
                    const int g = dt >> 1, i2 = (dt & 1) * 2;
                    mma16816h(o[dt], ph[js], fv[g][i2], fv[g][i2 + 1]);
                    mma16816h(o[dt], pl[js], fv[g][i2], fv[g][i2 + 1]);
                }
            }
        }
    }

    // ---- store O ----
#pragma unroll
    for (int dt = 0; dt < 8; dt++) {
        const int col = h * DH + dt * 8 + 2 * (l & 3);
        *(float2*)&out[((size_t)b * Tt + rowg) * Cc + col]     = make_float2(o[dt][0], o[dt][1]);
        *(float2*)&out[((size_t)b * Tt + rowg + 8) * Cc + col] = make_float2(o[dt][2], o[dt][3]);
    }
}

// ---------------------------------------------------------------------------
extern "C" void kernel_launch(void* const* d_in, const int* in_sizes, int n_in,
                              void* d_out, int out_size)
{
    const float* x    = (const float*)d_in[0];
    const float* W    = (const float*)d_in[1];
    const float* bias = (const float*)d_in[2];
    float* out        = (float*)d_out;
    (void)in_sizes; (void)n_in; (void)out_size;

    cvt_x<<<dim3(Mm / 64, Cc / 64), 256>>>(x);
    cvt_w<<<(Cc * N3) / 1024, 256>>>(W);

    dim3 g1(N3 / 128, Mm / 128);    // (18, 64)
    qkv_mma<<<g1, 128>>>(bias);

    dim3 g2(Tt / 64, Hh, Bb);       // (32, 12, 4)
    attn_mma<<<g2, 128>>>(out);
}

// round 15
// speedup vs baseline: 2.2315x; 1.6544x over previous
#include <cuda_runtime.h>
#include <cuda_fp16.h>
#include <cstdint>

// Problem constants (fixed by setup_inputs)
#define Bb 4
#define Tt 2048
#define Cc 768
#define Hh 12
#define DH 64
#define Mm (Bb * Tt)      // 8192
#define N3 (3 * Cc)       // 2304
#define NKSTEP (Cc / 16)  // 48

// ---------------------------------------------------------------------------
// Device scratch (single fp16 everywhere).
// x: fp16 TRANSPOSED [K][M]. W: fp16 [K][N]. Q (scaled), K, V: [B,H,T,D].
// ---------------------------------------------------------------------------
__device__ __half g_x[(size_t)Cc * Mm];
__device__ __half g_w[(size_t)Cc * N3];
__device__ __half g_q[(size_t)Bb * Hh * Tt * DH];
__device__ __half g_k[(size_t)Bb * Hh * Tt * DH];
__device__ __half g_v[(size_t)Bb * Hh * Tt * DH];

// ---------------------------------------------------------------------------
// Helpers
// ---------------------------------------------------------------------------
__device__ __forceinline__ uint32_t smem_u32(const void* p) {
    uint32_t a;
    asm("{ .reg .u64 t; cvta.to.shared.u64 t, %1; cvt.u32.u64 %0, t; }"
        : "=r"(a) : "l"(p));
    return a;
}
__device__ __forceinline__ void ldsm4(uint32_t r[4], uint32_t a) {
    asm volatile("ldmatrix.sync.aligned.m8n8.x4.shared.b16 {%0,%1,%2,%3}, [%4];"
                 : "=r"(r[0]), "=r"(r[1]), "=r"(r[2]), "=r"(r[3]) : "r"(a));
}
__device__ __forceinline__ void ldsm4t(uint32_t r[4], uint32_t a) {
    asm volatile("ldmatrix.sync.aligned.m8n8.x4.trans.shared.b16 {%0,%1,%2,%3}, [%4];"
                 : "=r"(r[0]), "=r"(r[1]), "=r"(r[2]), "=r"(r[3]) : "r"(a));
}
__device__ __forceinline__ void mma16816h(float* c, const uint32_t* a, uint32_t b0, uint32_t b1) {
    asm volatile(
        "mma.sync.aligned.m16n8k16.row.col.f32.f16.f16.f32 "
        "{%0,%1,%2,%3}, {%4,%5,%6,%7}, {%8,%9}, {%0,%1,%2,%3};"
        : "+f"(c[0]), "+f"(c[1]), "+f"(c[2]), "+f"(c[3])
        : "r"(a[0]), "r"(a[1]), "r"(a[2]), "r"(a[3]), "r"(b0), "r"(b1));
}
__device__ __forceinline__ uint32_t packh2(float x0, float x1) {
    uint32_t h;
    asm("cvt.rn.f16x2.f32 %0, %1, %2;" : "=r"(h) : "f"(x1), "f"(x0));
    return h;   // low halfword = x0
}

#define CP16(s, g) \
    asm volatile("cp.async.cg.shared.global [%0], [%1], 16;" :: "r"(s), "l"(g))
#define CP_COMMIT() asm volatile("cp.async.commit_group;" ::: "memory")
#define CP_WAIT0()  asm volatile("cp.async.wait_group 0;" ::: "memory")

#define SWZ(row, byteoff) ((byteoff) ^ (((row) & 7) << 4))

// ---------------------------------------------------------------------------
// cvt_x: fp32 x[M][K] -> fp16 TRANSPOSED [K][M]
// ---------------------------------------------------------------------------
__global__ __launch_bounds__(256) void cvt_x(const float* __restrict__ x) {
    __shared__ float S[64][65];
    const int m0 = blockIdx.x * 64, k0 = blockIdx.y * 64;
    const int tid = threadIdx.x;
#pragma unroll
    for (int i = 0; i < 4; i++) {
        const int c = tid + i * 256;
        const int row = c >> 4;
        const int c4 = (c & 15) * 4;
        float4 v = *(const float4*)&x[(size_t)(m0 + row) * Cc + k0 + c4];
        S[row][c4] = v.x; S[row][c4 + 1] = v.y; S[row][c4 + 2] = v.z; S[row][c4 + 3] = v.w;
    }
    __syncthreads();
#pragma unroll
    for (int i = 0; i < 2; i++) {
        const int c = tid + i * 256;
        const int k = c >> 3;
        const int mc = c & 7;
        uint32_t hw[4];
#pragma unroll
        for (int e = 0; e < 4; e++)
            hw[e] = packh2(S[mc * 8 + 2 * e][k], S[mc * 8 + 2 * e + 1][k]);
        const size_t g = (size_t)(k0 + k) * Mm + m0 + mc * 8;
        *(uint4*)&g_x[g] = make_uint4(hw[0], hw[1], hw[2], hw[3]);
    }
}
__global__ __launch_bounds__(256) void cvt_w(const float* __restrict__ W) {
    const size_t base = ((size_t)blockIdx.x * 256 + threadIdx.x) * 4;
    float4 v = *(const float4*)&W[base];
    *(uint2*)&g_w[base] = make_uint2(packh2(v.x, v.y), packh2(v.z, v.w));
}

// ---------------------------------------------------------------------------
// Kernel 1: qkv = x @ W + b, single fp16 mma.
// 128x128 block, 128 thr, 4 warps (2m x 2n), warp 64x64.
// 32KB static smem: 2 super-stages x 16KB; each = 2 sub-stages of 8KB
// (A @0, B @4096). Two k-steps per wait+sync.
// ---------------------------------------------------------------------------
__global__ __launch_bounds__(128) void qkv_mma(const float* __restrict__ bias) {
    __shared__ __align__(128) uint8_t smd[32768];
    const uint32_t uS = smem_u32(smd);

    const int tid = threadIdx.x;
    const int l   = tid & 31;
    const int w   = tid >> 5;
    const int wm  = w >> 1;
    const int wn  = w & 1;
    const int m0  = blockIdx.y * 128;
    const int n0  = blockIdx.x * 128;

    float acc[4][8][4];
#pragma unroll
    for (int i = 0; i < 4; i++)
#pragma unroll
        for (int j = 0; j < 8; j++)
#pragma unroll
            for (int r = 0; r < 4; r++) acc[i][j][r] = 0.f;

    const int cr = tid >> 3;
    const int cc = (tid & 7) * 2;
    const uint32_t so0 = (uint32_t)SWZ(cr, cr * 256 + cc * 16);
    const uint32_t so1 = (uint32_t)SWZ(cr, cr * 256 + cc * 16 + 16);

#define QKV_SUB(kb, bofs) do {                                                \
    const int _k = (kb) * 16 + cr;                                            \
    const uint32_t _b = uS + (bofs);                                          \
    const size_t _ga = (size_t)_k * Mm + m0 + cc * 8;                         \
    const size_t _gb = (size_t)_k * N3 + n0 + cc * 8;                         \
    CP16(_b + so0,        g_x + _ga);                                         \
    CP16(_b + so1,        g_x + _ga + 8);                                     \
    CP16(_b + 4096 + so0, g_w + _gb);                                         \
    CP16(_b + 4096 + so1, g_w + _gb + 8);                                     \
} while (0)

#define QKV_ISSUE2(kb, sst) do {                                              \
    QKV_SUB(kb, (sst) * 16384);                                               \
    QKV_SUB((kb) + 1, (sst) * 16384 + 8192);                                  \
    CP_COMMIT();                                                              \
} while (0)

    const int arow = (l & 7) + 8 * (l >> 4);
    const int abyt = wm * 128 + ((l >> 3) & 1) * 16;
    const int brow = (l & 15);
    const int bbyt = wn * 128 + (l >> 4) * 16;

    QKV_ISSUE2(0, 0);

    for (int kb2 = 0; kb2 < NKSTEP / 2; kb2++) {       // 24 rounds
        CP_WAIT0();
        __syncthreads();
        if (kb2 + 1 < NKSTEP / 2) QKV_ISSUE2(2 * (kb2 + 1), (kb2 + 1) & 1);

        const uint32_t superb = uS + (kb2 & 1) * 16384;
#pragma unroll
        for (int sub = 0; sub < 2; sub++) {
            const uint32_t sb = superb + sub * 8192;
            uint32_t fa[4][4], fb[4][4];
#pragma unroll
            for (int mt = 0; mt < 4; mt++)
                ldsm4t(fa[mt], sb + SWZ(arow, arow * 256 + abyt + mt * 32));
#pragma unroll
            for (int g = 0; g < 4; g++)
                ldsm4t(fb[g], sb + 4096 + SWZ(brow, brow * 256 + bbyt + g * 32));

#pragma unroll
            for (int mt = 0; mt < 4; mt++)
#pragma unroll
                for (int nt = 0; nt < 8; nt++) {
                    const int g = nt >> 1, i2 = (nt & 1) * 2;
                    mma16816h(acc[mt][nt], fa[mt], fb[g][i2], fb[g][i2 + 1]);
                }
        }
    }

    // ---- Epilogue (single fp16 outputs; Q scaled) ----
    const int which = n0 / Cc;                  // 0=Q,1=K,2=V
    const int nloc0 = n0 - which * Cc;
    const float scale = (which == 0) ? 0.125f : 1.0f;
    __half* dst = (which == 0) ? g_q : (which == 1) ? g_k : g_v;
    const int mrow = m0 + wm * 64 + (l >> 2);
    const int b_   = mrow >> 11;

#pragma unroll
    for (int mt = 0; mt < 4; mt++) {
        const int t1 = (mrow + mt * 16) & (Tt - 1);
#pragma unroll
        for (int nt = 0; nt < 8; nt++) {
            const int n  = nloc0 + wn * 64 + nt * 8 + 2 * (l & 3);
            const int hh = n >> 6;
            const int d  = n & 63;
            const float b0 = bias[which * Cc + n];
            const float b1 = bias[which * Cc + n + 1];
            const size_t i1 = (((size_t)b_ * Hh + hh) * Tt + t1) * DH + d;
            const size_t i2 = i1 + (size_t)8 * DH;
            *(uint32_t*)&dst[i1] = packh2((acc[mt][nt][0] + b0) * scale,
                                          (acc[mt][nt][1] + b1) * scale);
            *(uint32_t*)&dst[i2] = packh2((acc[mt][nt][2] + b0) * scale,
                                          (acc[mt][nt][3] + b1) * scale);
        }
    }
}

// ---------------------------------------------------------------------------
// Kernel 2: causal ReLU attention, single fp16 mma.
// BQ=64, BK=64 per sync round. Static 32KB smem: 2 super-stages x 16KB;
// each = 2 sub-tiles (8KB: K 4KB @0, V 4KB @4096). Q via direct LDG.
// Phase-interleaved: S(0);S(1); pack(0);PV(0); pack(1);PV(1).
// ---------------------------------------------------------------------------
__global__ __launch_bounds__(128) void attn_mma(float* __restrict__ out)
{
    __shared__ __align__(128) uint8_t sm[32768];
    const uint32_t uS = smem_u32(sm);

    const int tid = threadIdx.x;
    const int l   = tid & 31;
    const int w   = tid >> 5;
    const int qt  = (gridDim.x - 1) - blockIdx.x;    // 0..31, long first
    const int h   = blockIdx.y;
    const int b   = blockIdx.z;

    const size_t hb = ((size_t)b * Hh + h) * (size_t)Tt * DH;

#define ATT_ISSUE2(j64, sst) do {                                           \
    const uint32_t _sb = uS + (sst) * 16384;                                \
    _Pragma("unroll")                                                       \
    for (int _i = 0; _i < 4; _i++) {                                        \
        const int _c = tid + _i * 128;       /* 0..511 */                   \
        const int _row = _c >> 3;            /* 0..63  */                   \
        const int _c16 = _c & 7;                                            \
        const int _sr  = _row & 31;                                         \
        const uint32_t _so = ((_row & 32) ? 8192u : 0u)                     \
                           + SWZ(_sr, _sr * 128 + _c16 * 16);               \
        const size_t _g = hb + (size_t)((j64) * 64 + _row) * DH + _c16 * 8; \
        CP16(_sb + _so,        g_k + _g);                                   \
        CP16(_sb + 4096 + _so, g_v + _g);                                   \
    }                                                                       \
    CP_COMMIT();                                                            \
} while (0)

    ATT_ISSUE2(0, 0);                 // first 64 kv rows -> super-stage 0

    // Q fragments via direct LDG (single fp16; matches mma A-fragment layout)
    uint32_t fq[4][4];
    const int r0 = qt * 64 + w * 16 + (l >> 2);
    {
        const size_t qb0 = hb + (size_t)r0 * DH;
        const size_t qb1 = qb0 + (size_t)8 * DH;
#pragma unroll
        for (int ks = 0; ks < 4; ks++) {
            const int c0 = ks * 16 + (l & 3) * 2;
            fq[ks][0] = *(const uint32_t*)&g_q[qb0 + c0];
            fq[ks][1] = *(const uint32_t*)&g_q[qb1 + c0];
            fq[ks][2] = *(const uint32_t*)&g_q[qb0 + c0 + 8];
            fq[ks][3] = *(const uint32_t*)&g_q[qb1 + c0 + 8];
        }
    }

    float o[8][4];
#pragma unroll
    for (int i = 0; i < 8; i++)
#pragma unroll
        for (int r = 0; r < 4; r++) o[i][r] = 0.f;

    const int rowg = r0;

    for (int jo = 0; jo <= qt; jo++) {
        CP_WAIT0();
        __syncthreads();
        if (jo < qt) ATT_ISSUE2(jo + 1, (jo + 1) & 1);

        const uint32_t superb = uS + (jo & 1) * 16384;

        // ===== Phase A: S for BOTH sub-tiles =====
        float s[2][4][4];
#pragma unroll
        for (int sub = 0; sub < 2; sub++)
#pragma unroll
            for (int i = 0; i < 4; i++)
#pragma unroll
                for (int r = 0; r < 4; r++) s[sub][i][r] = 0.f;

        const int nrow = (l & 7) + 8 * (l >> 4);
#pragma unroll
        for (int sub = 0; sub < 2; sub++) {
            const uint32_t sb = superb + sub * 8192;
#pragma unroll
            for (int ks = 0; ks < 4; ks++) {
                uint32_t fk[2][4];
                const int cb = (ks * 16 + 8 * ((l >> 3) & 1)) * 2;
#pragma unroll
                for (int g = 0; g < 2; g++) {
                    const int rr = g * 16 + nrow;
                    ldsm4(fk[g], sb + SWZ(rr, rr * 128 + cb));
                }
#pragma unroll
                for (int nt = 0; nt < 4; nt++) {
                    const int g = nt >> 1, i2 = (nt & 1) * 2;
                    mma16816h(s[sub][nt], fq[ks], fk[g][i2], fk[g][i2 + 1]);
                }
            }
        }

        // ===== Phase B: mask/pack + PV per sub-tile =====
#pragma unroll
        for (int sub = 0; sub < 2; sub++) {
            const int j2 = 2 * jo + sub;
            const uint32_t sb = superb + sub * 8192;

            uint32_t ph[2][4];
            const bool nm = (j2 * 32 + 31 > qt * 64 + w * 16);
#pragma unroll
            for (int nt = 0; nt < 4; nt++) {
                const int colg = j2 * 32 + nt * 8 + 2 * (l & 3);
                float v0 = fmaxf(s[sub][nt][0], 0.f);
                float v1 = fmaxf(s[sub][nt][1], 0.f);
                float v2 = fmaxf(s[sub][nt][2], 0.f);
                float v3 = fmaxf(s[sub][nt][3], 0.f);
                if (nm) {
                    if (colg     > rowg)     v0 = 0.f;
                    if (colg + 1 > rowg)     v1 = 0.f;
                    if (colg     > rowg + 8) v2 = 0.f;
                    if (colg + 1 > rowg + 8) v3 = 0.f;
                }
                const int js = nt >> 1, pos = (nt & 1) * 2;
                ph[js][pos]     = packh2(v0, v1);
                ph[js][pos + 1] = packh2(v2, v3);
            }

#pragma unroll
            for (int js = 0; js < 2; js++) {
                uint32_t fv[4][4];
                const int vrow = js * 16 + (l & 15);
#pragma unroll
                for (int g = 0; g < 4; g++) {
                    const int cb = (g * 16 + (l >> 4) * 8) * 2;
                    ldsm4t(fv[g], sb + 4096 + SWZ(vrow, vrow * 128 + cb));
                }
#pragma unroll
                for (int dt = 0; dt < 8; dt++) {
                    const int g = dt >> 1, i2 = (dt & 1) * 2;
                    mma16816h(o[dt], ph[js], fv[g][i2], fv[g][i2 + 1]);
                }
            }
        }
    }

    // ---- store O ----
#pragma unroll
    for (int dt = 0; dt < 8; dt++) {
        const int col = h * DH + dt * 8 + 2 * (l & 3);
        *(float2*)&out[((size_t)b * Tt + rowg) * Cc + col]     = make_float2(o[dt][0], o[dt][1]);
        *(float2*)&out[((size_t)b * Tt + rowg + 8) * Cc + col] = make_float2(o[dt][2], o[dt][3]);
    }
}

// ---------------------------------------------------------------------------
extern "C" void kernel_launch(void* const* d_in, const int* in_sizes, int n_in,
                              void* d_out, int out_size)
{
    const float* x    = (const float*)d_in[0];
    const float* W    = (const float*)d_in[1];
    const float* bias = (const float*)d_in[2];
    float* out        = (float*)d_out;
    (void)in_sizes; (void)n_in; (void)out_size;

    cvt_x<<<dim3(Mm / 64, Cc / 64), 256>>>(x);
    cvt_w<<<(Cc * N3) / 1024, 256>>>(W);

    dim3 g1(N3 / 128, Mm / 128);    // (18, 64)
    qkv_mma<<<g1, 128>>>(bias);

    dim3 g2(Tt / 64, Hh, Bb);       // (32, 12, 4)
    attn_mma<<<g2, 128>>>(out);
}

// round 16
// speedup vs baseline: 2.2565x; 1.0112x over previous
#include <cuda_runtime.h>
#include <cuda_fp16.h>
#include <cstdint>

// Problem constants (fixed by setup_inputs)
#define Bb 4
#define Tt 2048
#define Cc 768
#define Hh 12
#define DH 64
#define Mm (Bb * Tt)      // 8192
#define N3 (3 * Cc)       // 2304
#define NKSTEP (Cc / 16)  // 48

// ---------------------------------------------------------------------------
// Device scratch (single fp16 everywhere).
// x: fp16 TRANSPOSED [K][M]. W: fp16 [K][N]. Q (scaled), K, V: [B,H,T,D].
// ---------------------------------------------------------------------------
__device__ __half g_x[(size_t)Cc * Mm];
__device__ __half g_w[(size_t)Cc * N3];
__device__ __half g_q[(size_t)Bb * Hh * Tt * DH];
__device__ __half g_k[(size_t)Bb * Hh * Tt * DH];
__device__ __half g_v[(size_t)Bb * Hh * Tt * DH];

// ---------------------------------------------------------------------------
// Helpers
// ---------------------------------------------------------------------------
__device__ __forceinline__ uint32_t smem_u32(const void* p) {
    uint32_t a;
    asm("{ .reg .u64 t; cvta.to.shared.u64 t, %1; cvt.u32.u64 %0, t; }"
        : "=r"(a) : "l"(p));
    return a;
}
__device__ __forceinline__ void ldsm4(uint32_t r[4], uint32_t a) {
    asm volatile("ldmatrix.sync.aligned.m8n8.x4.shared.b16 {%0,%1,%2,%3}, [%4];"
                 : "=r"(r[0]), "=r"(r[1]), "=r"(r[2]), "=r"(r[3]) : "r"(a));
}
__device__ __forceinline__ void ldsm4t(uint32_t r[4], uint32_t a) {
    asm volatile("ldmatrix.sync.aligned.m8n8.x4.trans.shared.b16 {%0,%1,%2,%3}, [%4];"
                 : "=r"(r[0]), "=r"(r[1]), "=r"(r[2]), "=r"(r[3]) : "r"(a));
}
__device__ __forceinline__ void mma16816h(float* c, const uint32_t* a, uint32_t b0, uint32_t b1) {
    asm volatile(
        "mma.sync.aligned.m16n8k16.row.col.f32.f16.f16.f32 "
        "{%0,%1,%2,%3}, {%4,%5,%6,%7}, {%8,%9}, {%0,%1,%2,%3};"
        : "+f"(c[0]), "+f"(c[1]), "+f"(c[2]), "+f"(c[3])
        : "r"(a[0]), "r"(a[1]), "r"(a[2]), "r"(a[3]), "r"(b0), "r"(b1));
}
__device__ __forceinline__ uint32_t packh2(float x0, float x1) {
    uint32_t h;
    asm("cvt.rn.f16x2.f32 %0, %1, %2;" : "=r"(h) : "f"(x1), "f"(x0));
    return h;   // low halfword = x0
}
__device__ __forceinline__ uint32_t relu_h2(uint32_t v) {
    uint32_t r;
    asm("max.f16x2 %0, %1, %2;" : "=r"(r) : "r"(v), "r"(0u));
    return r;
}

#define CP16(s, g) \
    asm volatile("cp.async.cg.shared.global [%0], [%1], 16;" :: "r"(s), "l"(g))
#define CP_COMMIT() asm volatile("cp.async.commit_group;" ::: "memory")
#define CP_WAIT0()  asm volatile("cp.async.wait_group 0;" ::: "memory")

#define SWZ(row, byteoff) ((byteoff) ^ (((row) & 7) << 4))

// ---------------------------------------------------------------------------
// cvt_x: fp32 x[M][K] -> fp16 TRANSPOSED [K][M]
// ---------------------------------------------------------------------------
__global__ __launch_bounds__(256) void cvt_x(const float* __restrict__ x) {
    __shared__ float S[64][65];
    const int m0 = blockIdx.x * 64, k0 = blockIdx.y * 64;
    const int tid = threadIdx.x;
#pragma unroll
    for (int i = 0; i < 4; i++) {
        const int c = tid + i * 256;
        const int row = c >> 4;
        const int c4 = (c & 15) * 4;
        float4 v = *(const float4*)&x[(size_t)(m0 + row) * Cc + k0 + c4];
        S[row][c4] = v.x; S[row][c4 + 1] = v.y; S[row][c4 + 2] = v.z; S[row][c4 + 3] = v.w;
    }
    __syncthreads();
#pragma unroll
    for (int i = 0; i < 2; i++) {
        const int c = tid + i * 256;
        const int k = c >> 3;
        const int mc = c & 7;
        uint32_t hw[4];
#pragma unroll
        for (int e = 0; e < 4; e++)
            hw[e] = packh2(S[mc * 8 + 2 * e][k], S[mc * 8 + 2 * e + 1][k]);
        const size_t g = (size_t)(k0 + k) * Mm + m0 + mc * 8;
        *(uint4*)&g_x[g] = make_uint4(hw[0], hw[1], hw[2], hw[3]);
    }
}
__global__ __launch_bounds__(256) void cvt_w(const float* __restrict__ W) {
    const size_t base = ((size_t)blockIdx.x * 256 + threadIdx.x) * 4;
    float4 v = *(const float4*)&W[base];
    *(uint2*)&g_w[base] = make_uint2(packh2(v.x, v.y), packh2(v.z, v.w));
}

// ---------------------------------------------------------------------------
// Kernel 1: qkv = x @ W + b, single fp16 mma (R15 mainloop).
// 128x128 block, 128 thr, 4 warps (2m x 2n), warp 64x64.
// 32KB static smem: 2 super-stages x 16KB (each 2 x 8KB: A @0, B @4096).
// ---------------------------------------------------------------------------
__global__ __launch_bounds__(128) void qkv_mma(const float* __restrict__ bias) {
    __shared__ __align__(128) uint8_t smd[32768];
    const uint32_t uS = smem_u32(smd);

    const int tid = threadIdx.x;
    const int l   = tid & 31;
    const int w   = tid >> 5;
    const int wm  = w >> 1;
    const int wn  = w & 1;
    const int m0  = blockIdx.y * 128;
    const int n0  = blockIdx.x * 128;

    float acc[4][8][4];
#pragma unroll
    for (int i = 0; i < 4; i++)
#pragma unroll
        for (int j = 0; j < 8; j++)
#pragma unroll
            for (int r = 0; r < 4; r++) acc[i][j][r] = 0.f;

    const int cr = tid >> 3;
    const int cc = (tid & 7) * 2;
    const uint32_t so0 = (uint32_t)SWZ(cr, cr * 256 + cc * 16);
    const uint32_t so1 = (uint32_t)SWZ(cr, cr * 256 + cc * 16 + 16);

#define QKV_SUB(kb, bofs) do {                                                \
    const int _k = (kb) * 16 + cr;                                            \
    const uint32_t _b = uS + (bofs);                                          \
    const size_t _ga = (size_t)_k * Mm + m0 + cc * 8;                         \
    const size_t _gb = (size_t)_k * N3 + n0 + cc * 8;                         \
    CP16(_b + so0,        g_x + _ga);                                         \
    CP16(_b + so1,        g_x + _ga + 8);                                     \
    CP16(_b + 4096 + so0, g_w + _gb);                                         \
    CP16(_b + 4096 + so1, g_w + _gb + 8);                                     \
} while (0)

#define QKV_ISSUE2(kb, sst) do {                                              \
    QKV_SUB(kb, (sst) * 16384);                                               \
    QKV_SUB((kb) + 1, (sst) * 16384 + 8192);                                  \
    CP_COMMIT();                                                              \
} while (0)

    const int arow = (l & 7) + 8 * (l >> 4);
    const int abyt = wm * 128 + ((l >> 3) & 1) * 16;
    const int brow = (l & 15);
    const int bbyt = wn * 128 + (l >> 4) * 16;

    QKV_ISSUE2(0, 0);

    for (int kb2 = 0; kb2 < NKSTEP / 2; kb2++) {       // 24 rounds
        CP_WAIT0();
        __syncthreads();
        if (kb2 + 1 < NKSTEP / 2) QKV_ISSUE2(2 * (kb2 + 1), (kb2 + 1) & 1);

        const uint32_t superb = uS + (kb2 & 1) * 16384;
#pragma unroll
        for (int sub = 0; sub < 2; sub++) {
            const uint32_t sb = superb + sub * 8192;
            uint32_t fa[4][4], fb[4][4];
#pragma unroll
            for (int mt = 0; mt < 4; mt++)
                ldsm4t(fa[mt], sb + SWZ(arow, arow * 256 + abyt + mt * 32));
#pragma unroll
            for (int g = 0; g < 4; g++)
                ldsm4t(fb[g], sb + 4096 + SWZ(brow, brow * 256 + bbyt + g * 32));

#pragma unroll
            for (int mt = 0; mt < 4; mt++)
#pragma unroll
                for (int nt = 0; nt < 8; nt++) {
                    const int g = nt >> 1, i2 = (nt & 1) * 2;
                    mma16816h(acc[mt][nt], fa[mt], fb[g][i2], fb[g][i2 + 1]);
                }
        }
    }

    // ---- Epilogue (single fp16 outputs; Q scaled; bias hoisted) ----
    const int which = n0 / Cc;                  // 0=Q,1=K,2=V
    const int nloc0 = n0 - which * Cc;
    const float scale = (which == 0) ? 0.125f : 1.0f;
    __half* dst = (which == 0) ? g_q : (which == 1) ? g_k : g_v;
    const int mrow = m0 + wm * 64 + (l >> 2);
    const int b_   = mrow >> 11;

    float bv0[8], bv1[8];
#pragma unroll
    for (int nt = 0; nt < 8; nt++) {
        const int n = nloc0 + wn * 64 + nt * 8 + 2 * (l & 3);
        bv0[nt] = bias[which * Cc + n];
        bv1[nt] = bias[which * Cc + n + 1];
    }

#pragma unroll
    for (int mt = 0; mt < 4; mt++) {
        const int t1 = (mrow + mt * 16) & (Tt - 1);
#pragma unroll
        for (int nt = 0; nt < 8; nt++) {
            const int n  = nloc0 + wn * 64 + nt * 8 + 2 * (l & 3);
            const int hh = n >> 6;
            const int d  = n & 63;
            const size_t i1 = (((size_t)b_ * Hh + hh) * Tt + t1) * DH + d;
            const size_t i2 = i1 + (size_t)8 * DH;
            *(uint32_t*)&dst[i1] = packh2((acc[mt][nt][0] + bv0[nt]) * scale,
                                          (acc[mt][nt][1] + bv1[nt]) * scale);
            *(uint32_t*)&dst[i2] = packh2((acc[mt][nt][2] + bv0[nt]) * scale,
                                          (acc[mt][nt][3] + bv1[nt]) * scale);
        }
    }
}

// ---------------------------------------------------------------------------
// Kernel 2: causal ReLU attention, single fp16 mma (R15 structure).
// BQ=64, BK=64 per sync round. Static 32KB smem: 2 super-stages x 16KB;
// each = 2 sub-tiles (8KB: K 4KB @0, V 4KB @4096). Q via direct LDG.
// Phase B fast path: pack-then-ReLU in f16x2 (bit-exact vs float path).
// ---------------------------------------------------------------------------
__global__ __launch_bounds__(128) void attn_mma(float* __restrict__ out)
{
    __shared__ __align__(128) uint8_t sm[32768];
    const uint32_t uS = smem_u32(sm);

    const int tid = threadIdx.x;
    const int l   = tid & 31;
    const int w   = tid >> 5;
    const int qt  = (gridDim.x - 1) - blockIdx.x;    // 0..31, long first
    const int h   = blockIdx.y;
    const int b   = blockIdx.z;

    const size_t hb = ((size_t)b * Hh + h) * (size_t)Tt * DH;

#define ATT_ISSUE2(j64, sst) do {                                           \
    const uint32_t _sb = uS + (sst) * 16384;                                \
    _Pragma("unroll")                                                       \
    for (int _i = 0; _i < 4; _i++) {                                        \
        const int _c = tid + _i * 128;       /* 0..511 */                   \
        const int _row = _c >> 3;            /* 0..63  */                   \
        const int _c16 = _c & 7;                                            \
        const int _sr  = _row & 31;                                         \
        const uint32_t _so = ((_row & 32) ? 8192u : 0u)                     \
                           + SWZ(_sr, _sr * 128 + _c16 * 16);               \
        const size_t _g = hb + (size_t)((j64) * 64 + _row) * DH + _c16 * 8; \
        CP16(_sb + _so,        g_k + _g);                                   \
        CP16(_sb + 4096 + _so, g_v + _g);                                   \
    }                                                                       \
    CP_COMMIT();                                                            \
} while (0)

    ATT_ISSUE2(0, 0);                 // first 64 kv rows -> super-stage 0

    // Q fragments via direct LDG (single fp16; matches mma A-fragment layout)
    uint32_t fq[4][4];
    const int r0 = qt * 64 + w * 16 + (l >> 2);
    {
        const size_t qb0 = hb + (size_t)r0 * DH;
        const size_t qb1 = qb0 + (size_t)8 * DH;
#pragma unroll
        for (int ks = 0; ks < 4; ks++) {
            const int c0 = ks * 16 + (l & 3) * 2;
            fq[ks][0] = *(const uint32_t*)&g_q[qb0 + c0];
            fq[ks][1] = *(const uint32_t*)&g_q[qb1 + c0];
            fq[ks][2] = *(const uint32_t*)&g_q[qb0 + c0 + 8];
            fq[ks][3] = *(const uint32_t*)&g_q[qb1 + c0 + 8];
        }
    }

    float o[8][4];
#pragma unroll
    for (int i = 0; i < 8; i++)
#pragma unroll
        for (int r = 0; r < 4; r++) o[i][r] = 0.f;

    const int rowg = r0;

    for (int jo = 0; jo <= qt; jo++) {
        CP_WAIT0();
        __syncthreads();
        if (jo < qt) ATT_ISSUE2(jo + 1, (jo + 1) & 1);

        const uint32_t superb = uS + (jo & 1) * 16384;

        // ===== Phase A: S for BOTH sub-tiles =====
        float s[2][4][4];
#pragma unroll
        for (int sub = 0; sub < 2; sub++)
#pragma unroll
            for (int i = 0; i < 4; i++)
#pragma unroll
                for (int r = 0; r < 4; r++) s[sub][i][r] = 0.f;

        const int nrow = (l & 7) + 8 * (l >> 4);
#pragma unroll
        for (int sub = 0; sub < 2; sub++) {
            const uint32_t sb = superb + sub * 8192;
#pragma unroll
            for (int ks = 0; ks < 4; ks++) {
                uint32_t fk[2][4];
                const int cb = (ks * 16 + 8 * ((l >> 3) & 1)) * 2;
#pragma unroll
                for (int g = 0; g < 2; g++) {
                    const int rr = g * 16 + nrow;
                    ldsm4(fk[g], sb + SWZ(rr, rr * 128 + cb));
                }
#pragma unroll
                for (int nt = 0; nt < 4; nt++) {
                    const int g = nt >> 1, i2 = (nt & 1) * 2;
                    mma16816h(s[sub][nt], fq[ks], fk[g][i2], fk[g][i2 + 1]);
                }
            }
        }

        // ===== Phase B: mask/pack + PV per sub-tile =====
#pragma unroll
        for (int sub = 0; sub < 2; sub++) {
            const int j2 = 2 * jo + sub;
            const uint32_t sb = superb + sub * 8192;

            uint32_t ph[2][4];
            const bool nm = (j2 * 32 + 31 > qt * 64 + w * 16);
            if (!nm) {
                // Fast path: pack then f16x2 ReLU (bit-exact vs float path)
#pragma unroll
                for (int nt = 0; nt < 4; nt++) {
                    const int js = nt >> 1, pos = (nt & 1) * 2;
                    ph[js][pos]     = relu_h2(packh2(s[sub][nt][0], s[sub][nt][1]));
                    ph[js][pos + 1] = relu_h2(packh2(s[sub][nt][2], s[sub][nt][3]));
                }
            } else {
#pragma unroll
                for (int nt = 0; nt < 4; nt++) {
                    const int colg = j2 * 32 + nt * 8 + 2 * (l & 3);
                    float v0 = fmaxf(s[sub][nt][0], 0.f);
                    float v1 = fmaxf(s[sub][nt][1], 0.f);
                    float v2 = fmaxf(s[sub][nt][2], 0.f);
                    float v3 = fmaxf(s[sub][nt][3], 0.f);
                    if (colg     > rowg)     v0 = 0.f;
                    if (colg + 1 > rowg)     v1 = 0.f;
                    if (colg     > rowg + 8) v2 = 0.f;
                    if (colg + 1 > rowg + 8) v3 = 0.f;
                    const int js = nt >> 1, pos = (nt & 1) * 2;
                    ph[js][pos]     = packh2(v0, v1);
                    ph[js][pos + 1] = packh2(v2, v3);
                }
            }

#pragma unroll
            for (int js = 0; js < 2; js++) {
                uint32_t fv[4][4];
                const int vrow = js * 16 + (l & 15);
#pragma unroll
                for (int g = 0; g < 4; g++) {
                    const int cb = (g * 16 + (l >> 4) * 8) * 2;
                    ldsm4t(fv[g], sb + 4096 + SWZ(vrow, vrow * 128 + cb));
                }
#pragma unroll
                for (int dt = 0; dt < 8; dt++) {
                    const int g = dt >> 1, i2 = (dt & 1) * 2;
                    mma16816h(o[dt], ph[js], fv[g][i2], fv[g][i2 + 1]);
                }
            }
        }
    }

    // ---- store O ----
#pragma unroll
    for (int dt = 0; dt < 8; dt++) {
        const int col = h * DH + dt * 8 + 2 * (l & 3);
        *(float2*)&out[((size_t)b * Tt + rowg) * Cc + col]     = make_float2(o[dt][0], o[dt][1]);
        *(float2*)&out[((size_t)b * Tt + rowg + 8) * Cc + col] = make_float2(o[dt][2], o[dt][3]);
    }
}

// ---------------------------------------------------------------------------
extern "C" void kernel_launch(void* const* d_in, const int* in_sizes, int n_in,
                              void* d_out, int out_size)
{
    const float* x    = (const float*)d_in[0];
    const float* W    = (const float*)d_in[1];
    const float* bias = (const float*)d_in[2];
    float* out        = (float*)d_out;
    (void)in_sizes; (void)n_in; (void)out_size;

    cvt_x<<<dim3(Mm / 64, Cc / 64), 256>>>(x);
    cvt_w<<<(Cc * N3) / 1024, 256>>>(W);

    dim3 g1(N3 / 128, Mm / 128);    // (18, 64)
    qkv_mma<<<g1, 128>>>(bias);

    dim3 g2(Tt / 64, Hh, Bb);       // (32, 12, 4)
    attn_mma<<<g2, 128>>>(out);
}

// round 17
// speedup vs baseline: 2.2573x; 1.0004x over previous
#include <cuda_runtime.h>
#include <cuda_fp16.h>
#include <cstdint>

// Problem constants (fixed by setup_inputs)
#define Bb 4
#define Tt 2048
#define Cc 768
#define Hh 12
#define DH 64
#define Mm (Bb * Tt)      // 8192
#define N3 (3 * Cc)       // 2304
#define NKSTEP (Cc / 16)  // 48

// ---------------------------------------------------------------------------
// Device scratch (single fp16 everywhere).
// x: fp16 TRANSPOSED [K][M]. W: fp16 [K][N]. Q (scaled), K, V: [B,H,T,D].
// ---------------------------------------------------------------------------
__device__ __half g_x[(size_t)Cc * Mm];
__device__ __half g_w[(size_t)Cc * N3];
__device__ __half g_q[(size_t)Bb * Hh * Tt * DH];
__device__ __half g_k[(size_t)Bb * Hh * Tt * DH];
__device__ __half g_v[(size_t)Bb * Hh * Tt * DH];

// ---------------------------------------------------------------------------
// Helpers
// ---------------------------------------------------------------------------
__device__ __forceinline__ uint32_t smem_u32(const void* p) {
    uint32_t a;
    asm("{ .reg .u64 t; cvta.to.shared.u64 t, %1; cvt.u32.u64 %0, t; }"
        : "=r"(a) : "l"(p));
    return a;
}
__device__ __forceinline__ void ldsm4(uint32_t r[4], uint32_t a) {
    asm volatile("ldmatrix.sync.aligned.m8n8.x4.shared.b16 {%0,%1,%2,%3}, [%4];"
                 : "=r"(r[0]), "=r"(r[1]), "=r"(r[2]), "=r"(r[3]) : "r"(a));
}
__device__ __forceinline__ void ldsm4t(uint32_t r[4], uint32_t a) {
    asm volatile("ldmatrix.sync.aligned.m8n8.x4.trans.shared.b16 {%0,%1,%2,%3}, [%4];"
                 : "=r"(r[0]), "=r"(r[1]), "=r"(r[2]), "=r"(r[3]) : "r"(a));
}
__device__ __forceinline__ void mma16816h(float* c, const uint32_t* a, uint32_t b0, uint32_t b1) {
    asm volatile(
        "mma.sync.aligned.m16n8k16.row.col.f32.f16.f16.f32 "
        "{%0,%1,%2,%3}, {%4,%5,%6,%7}, {%8,%9}, {%0,%1,%2,%3};"
        : "+f"(c[0]), "+f"(c[1]), "+f"(c[2]), "+f"(c[3])
        : "r"(a[0]), "r"(a[1]), "r"(a[2]), "r"(a[3]), "r"(b0), "r"(b1));
}
__device__ __forceinline__ uint32_t packh2(float x0, float x1) {
    uint32_t h;
    asm("cvt.rn.f16x2.f32 %0, %1, %2;" : "=r"(h) : "f"(x1), "f"(x0));
    return h;   // low halfword = x0
}
__device__ __forceinline__ uint32_t relu_h2(uint32_t v) {
    uint32_t r;
    asm("max.f16x2 %0, %1, %2;" : "=r"(r) : "r"(v), "r"(0u));
    return r;
}

#define CP16(s, g) \
    asm volatile("cp.async.cg.shared.global [%0], [%1], 16;" :: "r"(s), "l"(g))
#define CP_COMMIT() asm volatile("cp.async.commit_group;" ::: "memory")
#define CP_WAIT0()  asm volatile("cp.async.wait_group 0;" ::: "memory")

#define SWZ(row, byteoff) ((byteoff) ^ (((row) & 7) << 4))

// ---------------------------------------------------------------------------
// cvt_x: fp32 x[M][K] -> fp16 TRANSPOSED [K][M]
// ---------------------------------------------------------------------------
__global__ __launch_bounds__(256) void cvt_x(const float* __restrict__ x) {
    __shared__ float S[64][65];
    const int m0 = blockIdx.x * 64, k0 = blockIdx.y * 64;
    const int tid = threadIdx.x;
#pragma unroll
    for (int i = 0; i < 4; i++) {
        const int c = tid + i * 256;
        const int row = c >> 4;
        const int c4 = (c & 15) * 4;
        float4 v = *(const float4*)&x[(size_t)(m0 + row) * Cc + k0 + c4];
        S[row][c4] = v.x; S[row][c4 + 1] = v.y; S[row][c4 + 2] = v.z; S[row][c4 + 3] = v.w;
    }
    __syncthreads();
#pragma unroll
    for (int i = 0; i < 2; i++) {
        const int c = tid + i * 256;
        const int k = c >> 3;
        const int mc = c & 7;
        uint32_t hw[4];
#pragma unroll
        for (int e = 0; e < 4; e++)
            hw[e] = packh2(S[mc * 8 + 2 * e][k], S[mc * 8 + 2 * e + 1][k]);
        const size_t g = (size_t)(k0 + k) * Mm + m0 + mc * 8;
        *(uint4*)&g_x[g] = make_uint4(hw[0], hw[1], hw[2], hw[3]);
    }
}
__global__ __launch_bounds__(256) void cvt_w(const float* __restrict__ W) {
    const size_t base = ((size_t)blockIdx.x * 256 + threadIdx.x) * 4;
    float4 v = *(const float4*)&W[base];
    *(uint2*)&g_w[base] = make_uint2(packh2(v.x, v.y), packh2(v.z, v.w));
}

// ---------------------------------------------------------------------------
// Kernel 1: qkv = x @ W + b, single fp16 mma.
// 128x128 block, 128 thr, 4 warps (2m x 2n), warp 64x64.
// 64KB DYNAMIC smem: 2 super-stages x 32KB; each = 4 sub-stages of 8KB
// (A @0, B @4096). FOUR k-steps per wait+sync (12 rounds).
// ---------------------------------------------------------------------------
__global__ __launch_bounds__(128) void qkv_mma(const float* __restrict__ bias) {
    extern __shared__ __align__(128) uint8_t smd[];
    const uint32_t uS = smem_u32(smd);

    const int tid = threadIdx.x;
    const int l   = tid & 31;
    const int w   = tid >> 5;
    const int wm  = w >> 1;
    const int wn  = w & 1;
    const int m0  = blockIdx.y * 128;
    const int n0  = blockIdx.x * 128;

    float acc[4][8][4];
#pragma unroll
    for (int i = 0; i < 4; i++)
#pragma unroll
        for (int j = 0; j < 8; j++)
#pragma unroll
            for (int r = 0; r < 4; r++) acc[i][j][r] = 0.f;

    const int cr = tid >> 3;
    const int cc = (tid & 7) * 2;
    const uint32_t so0 = (uint32_t)SWZ(cr, cr * 256 + cc * 16);
    const uint32_t so1 = (uint32_t)SWZ(cr, cr * 256 + cc * 16 + 16);

#define QKV_SUB(kb, bofs) do {                                                \
    const int _k = (kb) * 16 + cr;                                            \
    const uint32_t _b = uS + (bofs);                                          \
    const size_t _ga = (size_t)_k * Mm + m0 + cc * 8;                         \
    const size_t _gb = (size_t)_k * N3 + n0 + cc * 8;                         \
    CP16(_b + so0,        g_x + _ga);                                         \
    CP16(_b + so1,        g_x + _ga + 8);                                     \
    CP16(_b + 4096 + so0, g_w + _gb);                                         \
    CP16(_b + 4096 + so1, g_w + _gb + 8);                                     \
} while (0)

#define QKV_ISSUE4(kb, sst) do {                                              \
    QKV_SUB(kb,       (sst) * 32768);                                         \
    QKV_SUB((kb) + 1, (sst) * 32768 + 8192);                                  \
    QKV_SUB((kb) + 2, (sst) * 32768 + 16384);                                 \
    QKV_SUB((kb) + 3, (sst) * 32768 + 24576);                                 \
    CP_COMMIT();                                                              \
} while (0)

    const int arow = (l & 7) + 8 * (l >> 4);
    const int abyt = wm * 128 + ((l >> 3) & 1) * 16;
    const int brow = (l & 15);
    const int bbyt = wn * 128 + (l >> 4) * 16;

    QKV_ISSUE4(0, 0);

    for (int kb4 = 0; kb4 < NKSTEP / 4; kb4++) {       // 12 rounds
        CP_WAIT0();
        __syncthreads();
        if (kb4 + 1 < NKSTEP / 4) QKV_ISSUE4(4 * (kb4 + 1), (kb4 + 1) & 1);

        const uint32_t superb = uS + (kb4 & 1) * 32768;
#pragma unroll
        for (int sub = 0; sub < 4; sub++) {
            const uint32_t sb = superb + sub * 8192;
            uint32_t fa[4][4], fb[4][4];
#pragma unroll
            for (int mt = 0; mt < 4; mt++)
                ldsm4t(fa[mt], sb + SWZ(arow, arow * 256 + abyt + mt * 32));
#pragma unroll
            for (int g = 0; g < 4; g++)
                ldsm4t(fb[g], sb + 4096 + SWZ(brow, brow * 256 + bbyt + g * 32));

#pragma unroll
            for (int mt = 0; mt < 4; mt++)
#pragma unroll
                for (int nt = 0; nt < 8; nt++) {
                    const int g = nt >> 1, i2 = (nt & 1) * 2;
                    mma16816h(acc[mt][nt], fa[mt], fb[g][i2], fb[g][i2 + 1]);
                }
        }
    }

    // ---- Epilogue (single fp16 outputs; Q scaled; bias hoisted) ----
    const int which = n0 / Cc;                  // 0=Q,1=K,2=V
    const int nloc0 = n0 - which * Cc;
    const float scale = (which == 0) ? 0.125f : 1.0f;
    __half* dst = (which == 0) ? g_q : (which == 1) ? g_k : g_v;
    const int mrow = m0 + wm * 64 + (l >> 2);
    const int b_   = mrow >> 11;

    float bv0[8], bv1[8];
#pragma unroll
    for (int nt = 0; nt < 8; nt++) {
        const int n = nloc0 + wn * 64 + nt * 8 + 2 * (l & 3);
        bv0[nt] = bias[which * Cc + n];
        bv1[nt] = bias[which * Cc + n + 1];
    }

#pragma unroll
    for (int mt = 0; mt < 4; mt++) {
        const int t1 = (mrow + mt * 16) & (Tt - 1);
#pragma unroll
        for (int nt = 0; nt < 8; nt++) {
            const int n  = nloc0 + wn * 64 + nt * 8 + 2 * (l & 3);
            const int hh = n >> 6;
            const int d  = n & 63;
            const size_t i1 = (((size_t)b_ * Hh + hh) * Tt + t1) * DH + d;
            const size_t i2 = i1 + (size_t)8 * DH;
            *(uint32_t*)&dst[i1] = packh2((acc[mt][nt][0] + bv0[nt]) * scale,
                                          (acc[mt][nt][1] + bv1[nt]) * scale);
            *(uint32_t*)&dst[i2] = packh2((acc[mt][nt][2] + bv0[nt]) * scale,
                                          (acc[mt][nt][3] + bv1[nt]) * scale);
        }
    }
}

// ---------------------------------------------------------------------------
// Kernel 2: causal ReLU attention, single fp16 mma.
// BQ=64, BK=128 per sync round (4 x 32-row sub-tiles). 64KB DYNAMIC smem:
// 2 super-stages x 32KB; each = 4 sub-tiles (8KB: K 4KB @0, V 4KB @4096).
// Q via direct LDG. Per pair: S(a);S(b); pack(a);PV(a); pack(b);PV(b).
// Remainder pair guarded (ntile is even, may not be multiple of 4).
// ---------------------------------------------------------------------------
__global__ __launch_bounds__(128) void attn_mma(float* __restrict__ out)
{
    extern __shared__ __align__(128) uint8_t smd[];
    const uint32_t uS = smem_u32(smd);

    const int tid = threadIdx.x;
    const int l   = tid & 31;
    const int w   = tid >> 5;
    const int qt  = (gridDim.x - 1) - blockIdx.x;    // 0..31, long first
    const int h   = blockIdx.y;
    const int b   = blockIdx.z;

    const size_t hb = ((size_t)b * Hh + h) * (size_t)Tt * DH;

// Load 128 kv rows (rows r128*128 .. +127) into super-stage sst.
#define ATT_ISSUE4(r128, sst) do {                                          \
    const uint32_t _sb = uS + (sst) * 32768;                                \
    _Pragma("unroll")                                                       \
    for (int _i = 0; _i < 8; _i++) {                                        \
        const int _c = tid + _i * 128;       /* 0..1023 */                  \
        const int _row = _c >> 3;            /* 0..127  */                  \
        const int _c16 = _c & 7;                                            \
        const int _sr  = _row & 31;                                         \
        const uint32_t _so = (uint32_t)(_row >> 5) * 8192u                  \
                           + SWZ(_sr, _sr * 128 + _c16 * 16);               \
        const size_t _g = hb + (size_t)((r128) * 128 + _row) * DH + _c16 * 8; \
        CP16(_sb + _so,        g_k + _g);                                   \
        CP16(_sb + 4096 + _so, g_v + _g);                                   \
    }                                                                       \
    CP_COMMIT();                                                            \
} while (0)

    const int ntile = 2 * (qt + 1);      // 32-row sub-tiles, even, 2..64
    const int R = (qt + 2) / 2;          // 128-row rounds = ceil(ntile/4)

    ATT_ISSUE4(0, 0);

    // Q fragments via direct LDG (single fp16; matches mma A-fragment layout)
    uint32_t fq[4][4];
    const int r0 = qt * 64 + w * 16 + (l >> 2);
    {
        const size_t qb0 = hb + (size_t)r0 * DH;
        const size_t qb1 = qb0 + (size_t)8 * DH;
#pragma unroll
        for (int ks = 0; ks < 4; ks++) {
            const int c0 = ks * 16 + (l & 3) * 2;
            fq[ks][0] = *(const uint32_t*)&g_q[qb0 + c0];
            fq[ks][1] = *(const uint32_t*)&g_q[qb1 + c0];
            fq[ks][2] = *(const uint32_t*)&g_q[qb0 + c0 + 8];
            fq[ks][3] = *(const uint32_t*)&g_q[qb1 + c0 + 8];
        }
    }

    float o[8][4];
#pragma unroll
    for (int i = 0; i < 8; i++)
#pragma unroll
        for (int r = 0; r < 4; r++) o[i][r] = 0.f;

    const int rowg = r0;
    const int nrow = (l & 7) + 8 * (l >> 4);

// Process a pair of 32-row sub-tiles (j2 = jbase, jbase+1) from super-stage
// base 'superb', sub-tile slots 'slot' and 'slot+1'.
#define PROCESS_PAIR(superb, slot, jbase) do {                               \
    float s[2][4][4];                                                        \
    _Pragma("unroll")                                                        \
    for (int sub = 0; sub < 2; sub++)                                        \
        _Pragma("unroll")                                                    \
        for (int i = 0; i < 4; i++)                                          \
            _Pragma("unroll")                                                \
            for (int r = 0; r < 4; r++) s[sub][i][r] = 0.f;                  \
    _Pragma("unroll")                                                        \
    for (int sub = 0; sub < 2; sub++) {                                      \
        const uint32_t sb = (superb) + ((slot) + sub) * 8192;                \
        _Pragma("unroll")                                                    \
        for (int ks = 0; ks < 4; ks++) {                                     \
            uint32_t fk[2][4];                                               \
            const int cb = (ks * 16 + 8 * ((l >> 3) & 1)) * 2;               \
            _Pragma("unroll")                                                \
            for (int g = 0; g < 2; g++) {                                    \
                const int rr = g * 16 + nrow;                                \
                ldsm4(fk[g], sb + SWZ(rr, rr * 128 + cb));                   \
            }                                                                \
            _Pragma("unroll")                                                \
            for (int nt = 0; nt < 4; nt++) {                                 \
                const int g = nt >> 1, i2 = (nt & 1) * 2;                    \
                mma16816h(s[sub][nt], fq[ks], fk[g][i2], fk[g][i2 + 1]);     \
            }                                                                \
        }                                                                    \
    }                                                                        \
    _Pragma("unroll")                                                        \
    for (int sub = 0; sub < 2; sub++) {                                      \
        const int j2 = (jbase) + sub;                                        \
        const uint32_t sb = (superb) + ((slot) + sub) * 8192;                \
        uint32_t ph[2][4];                                                   \
        const bool nm = (j2 * 32 + 31 > qt * 64 + w * 16);                   \
        if (!nm) {                                                           \
            _Pragma("unroll")                                                \
            for (int nt = 0; nt < 4; nt++) {                                 \
                const int js = nt >> 1, pos = (nt & 1) * 2;                  \
                ph[js][pos]     = relu_h2(packh2(s[sub][nt][0], s[sub][nt][1])); \
                ph[js][pos + 1] = relu_h2(packh2(s[sub][nt][2], s[sub][nt][3])); \
            }                                                                \
        } else {                                                             \
            _Pragma("unroll")                                                \
            for (int nt = 0; nt < 4; nt++) {                                 \
                const int colg = j2 * 32 + nt * 8 + 2 * (l & 3);             \
                float v0 = fmaxf(s[sub][nt][0], 0.f);                        \
                float v1 = fmaxf(s[sub][nt][1], 0.f);                        \
                float v2 = fmaxf(s[sub][nt][2], 0.f);                        \
                float v3 = fmaxf(s[sub][nt][3], 0.f);                        \
                if (colg     > rowg)     v0 = 0.f;                           \
                if (colg + 1 > rowg)     v1 = 0.f;                           \
                if (colg     > rowg + 8) v2 = 0.f;                           \
                if (colg + 1 > rowg + 8) v3 = 0.f;                           \
                const int js = nt >> 1, pos = (nt & 1) * 2;                  \
                ph[js][pos]     = packh2(v0, v1);                            \
                ph[js][pos + 1] = packh2(v2, v3);                            \
            }                                                                \
        }                                                                    \
        _Pragma("unroll")                                                    \
        for (int js = 0; js < 2; js++) {                                     \
            uint32_t fv[4][4];                                               \
            const int vrow = js * 16 + (l & 15);                             \
            _Pragma("unroll")                                                \
            for (int g = 0; g < 4; g++) {                                    \
                const int cb = (g * 16 + (l >> 4) * 8) * 2;                  \
                ldsm4t(fv[g], sb + 4096 + SWZ(vrow, vrow * 128 + cb));       \
            }                                                                \
            _Pragma("unroll")                                                \
            for (int dt = 0; dt < 8; dt++) {                                 \
                const int g = dt >> 1, i2 = (dt & 1) * 2;                    \
                mma16816h(o[dt], ph[js], fv[g][i2], fv[g][i2 + 1]);          \
            }                                                                \
        }                                                                    \
    }                                                                        \
} while (0)

    for (int r = 0; r < R; r++) {
        CP_WAIT0();
        __syncthreads();
        if (r + 1 < R) ATT_ISSUE4(r + 1, (r + 1) & 1);

        const uint32_t superb = uS + (r & 1) * 32768;
        PROCESS_PAIR(superb, 0, 4 * r);
        if (4 * r + 2 < ntile)
            PROCESS_PAIR(superb, 2, 4 * r + 2);
    }

    // ---- store O ----
#pragma unroll
    for (int dt = 0; dt < 8; dt++) {
        const int col = h * DH + dt * 8 + 2 * (l & 3);
        *(float2*)&out[((size_t)b * Tt + rowg) * Cc + col]     = make_float2(o[dt][0], o[dt][1]);
        *(float2*)&out[((size_t)b * Tt + rowg + 8) * Cc + col] = make_float2(o[dt][2], o[dt][3]);
    }
}

// ---------------------------------------------------------------------------
extern "C" void kernel_launch(void* const* d_in, const int* in_sizes, int n_in,
                              void* d_out, int out_size)
{
    const float* x    = (const float*)d_in[0];
    const float* W    = (const float*)d_in[1];
    const float* bias = (const float*)d_in[2];
    float* out        = (float*)d_out;
    (void)in_sizes; (void)n_in; (void)out_size;

    // Unlock 64KB dynamic smem (idempotent; not a stream operation).
    cudaFuncSetAttribute(qkv_mma,  cudaFuncAttributeMaxDynamicSharedMemorySize, 65536);
    cudaFuncSetAttribute(attn_mma, cudaFuncAttributeMaxDynamicSharedMemorySize, 65536);

    cvt_x<<<dim3(Mm / 64, Cc / 64), 256>>>(x);
    cvt_w<<<(Cc * N3) / 1024, 256>>>(W);

    dim3 g1(N3 / 128, Mm / 128);    // (18, 64)
    qkv_mma<<<g1, 128, 65536>>>(bias);

    dim3 g2(Tt / 64, Hh, Bb);       // (32, 12, 4)
    attn_mma<<<g2, 128, 65536>>>(out);
}